// round 10
// baseline (speedup 1.0000x reference)
#include <cuda_runtime.h>
#include <cstdint>
#include <math.h>

#define SEQLEN   2048
#define HIDDEN   4096
#define NUM_HEADS 32
#define NUM_KV_HEADS 2
#define HEAD_DIM 128
#define QKV_OUT  ((NUM_HEADS + 2 * NUM_KV_HEADS) * HEAD_DIM)   // 4608
#define NQ       (NUM_HEADS * HEAD_DIM)                        // 4096
#define NKV      (NUM_KV_HEADS * HEAD_DIM)                     // 256
#define REP      (NUM_HEADS / NUM_KV_HEADS)                    // 16

// Scratch (device globals; no allocation allowed in kernel_launch)
__device__ float g_qkv[SEQLEN * QKV_OUT];        // ~37.7 MB
__device__ float g_attn[SEQLEN * NQ];            // ~33.5 MB
__device__ float g_vt[NUM_KV_HEADS * HEAD_DIM * SEQLEN];  // 2 MB, V dim-major

// ===========================================================================
// helpers
// ===========================================================================
__device__ __forceinline__ float tf32_round(float f) {
    uint32_t u;
    asm("cvt.rna.tf32.f32 %0, %1;" : "=r"(u) : "f"(f));
    return __uint_as_float(u);
}
__device__ __forceinline__ uint32_t tf32_round_u(uint32_t x) {
    uint32_t u;
    asm("cvt.rna.tf32.f32 %0, %1;" : "=r"(u) : "f"(__uint_as_float(x)));
    return u;
}
__device__ __forceinline__ uint32_t smem_u32(const void* p) {
    uint32_t a;
    asm("{ .reg .u64 t; cvta.to.shared.u64 t, %1; cvt.u32.u64 %0, t; }"
        : "=r"(a) : "l"(p));
    return a;
}
__device__ __forceinline__ void cp_async16(uint32_t dst, const void* src) {
    asm volatile("cp.async.cg.shared.global [%0], [%1], 16;" :: "r"(dst), "l"(src));
}
#define CP_COMMIT() asm volatile("cp.async.commit_group;" ::: "memory")
#define CP_WAIT1()  asm volatile("cp.async.wait_group 1;" ::: "memory")
#define CP_WAIT0()  asm volatile("cp.async.wait_group 0;" ::: "memory")

__device__ __forceinline__ void mma_tf32(float* c, const uint32_t* a, const uint32_t* b) {
    asm volatile(
        "mma.sync.aligned.m16n8k8.row.col.f32.tf32.tf32.f32 "
        "{%0,%1,%2,%3}, {%4,%5,%6,%7}, {%8,%9}, {%0,%1,%2,%3};"
        : "+f"(c[0]), "+f"(c[1]), "+f"(c[2]), "+f"(c[3])
        : "r"(a[0]), "r"(a[1]), "r"(a[2]), "r"(a[3]), "r"(b[0]), "r"(b[1]));
}
__device__ __forceinline__ void ldsm_x4(uint32_t& r0, uint32_t& r1,
                                        uint32_t& r2, uint32_t& r3, uint32_t addr) {
    asm volatile("ldmatrix.sync.aligned.m8n8.x4.shared.b16 {%0,%1,%2,%3}, [%4];"
        : "=r"(r0), "=r"(r1), "=r"(r2), "=r"(r3) : "r"(addr));
}

// ===========================================================================
// Fused RoPE + tf32 rounding of qkv (in place) + dim-major V copy to g_vt.
// ===========================================================================
__global__ void rope_round_kernel(const float* __restrict__ cosb,
                                  const float* __restrict__ sinb)
{
    const int HALF = QKV_OUT / 2;
    int idx = blockIdx.x * blockDim.x + threadIdx.x;
    if (idx >= SEQLEN * HALF) return;
    int s = idx / HALF;
    int c = (idx - s * HALF) * 2;
    float2* p = (float2*)(g_qkv + (size_t)s * QKV_OUT + c);
    float2 v = *p;
    int head = c >> 7, dim = c & 127;
    if (head < NUM_HEADS + NUM_KV_HEADS && dim < 64) {
        int pair = dim >> 1;
        float cs = cosb[s * 64 + pair];
        float sn = sinb[s * 64 + pair];
        float x0 = v.x, x1 = v.y;
        v.x = x0 * cs - x1 * sn;
        v.y = x1 * cs + x0 * sn;
    }
    v.x = tf32_round(v.x);
    v.y = tf32_round(v.y);
    *p = v;
    if (head >= NUM_HEADS + NUM_KV_HEADS) {   // V heads -> dim-major copy
        int kvh = head - (NUM_HEADS + NUM_KV_HEADS);
        g_vt[((size_t)(kvh * HEAD_DIM + dim))     * SEQLEN + s] = v.x;
        g_vt[((size_t)(kvh * HEAD_DIM + dim + 1)) * SEQLEN + s] = v.y;
    }
}

// ===========================================================================
// tf32 mma.sync GEMM: C[M,N] = A[M,K] @ B[K,N] (+bias)
// Raw fp32 inputs; operands tf32-rounded (cvt.rna) in-register at frag load,
// eliminating the separate rounding prepasses.
// ===========================================================================
#define ASTR 36
#define BSTR 136
#define A_FL (128 * ASTR)
#define B_FL (32 * BSTR)
#define STAGE_FL (A_FL + B_FL)
#define GSMEM_BYTES (3 * STAGE_FL * 4)

template <bool HAS_BIAS>
__global__ __launch_bounds__(256)
void gemm_mma(const float* __restrict__ A, const float* __restrict__ B,
              const float* __restrict__ bias, float* __restrict__ C,
              int K, int ldb, int N)
{
    extern __shared__ float smem[];
    const uint32_t sbase = smem_u32(smem);

    const int tid  = threadIdx.x;
    const int warp = tid >> 5;
    const int lane = tid & 31;
    const int g    = lane >> 2;
    const int t    = lane & 3;
    const int wm   = warp & 1;
    const int wn   = warp >> 1;
    const int brow = blockIdx.y * 128;
    const int n0   = blockIdx.x * 128;

    const int ga_row = lane & 15;
    const int ga_col = (lane >> 4) << 2;

    auto load_stage = [&](int s, int k0) {
        const float* Ap = A + (size_t)brow * K + k0;
        const float* Bp = B + (size_t)k0 * ldb + n0;
        const uint32_t sA = sbase + (uint32_t)s * (STAGE_FL * 4);
        const uint32_t sB = sA + A_FL * 4;
        #pragma unroll
        for (int p = 0; p < 4; p++) {
            int id = tid + p * 256;
            int r = id >> 3, c = (id & 7) << 2;
            cp_async16(sA + (uint32_t)(r * ASTR + c) * 4, Ap + (size_t)r * K + c);
        }
        #pragma unroll
        for (int p = 0; p < 4; p++) {
            int id = tid + p * 256;
            int r = id >> 5, c = (id & 31) << 2;
            cp_async16(sB + (uint32_t)(r * BSTR + c) * 4, Bp + (size_t)r * ldb + c);
        }
    };

    const int iters = K / 32;
    load_stage(0, 0);  CP_COMMIT();
    load_stage(1, 32); CP_COMMIT();

    float acc[4][4][4];
    #pragma unroll
    for (int mt = 0; mt < 4; mt++)
        #pragma unroll
        for (int nt = 0; nt < 4; nt++)
            #pragma unroll
            for (int q = 0; q < 4; q++) acc[mt][nt][q] = 0.0f;

    for (int i = 0; i < iters; i++) {
        CP_WAIT1();
        __syncthreads();
        if (i + 2 < iters) load_stage((i + 2) % 3, (i + 2) * 32);
        CP_COMMIT();

        const uint32_t sA = sbase + (uint32_t)(i % 3) * (STAGE_FL * 4);
        const float* Bs = smem + (i % 3) * STAGE_FL + A_FL;

        #pragma unroll
        for (int kk = 0; kk < 4; kk++) {
            const int k = kk * 8;
            uint32_t a[4][4];
            #pragma unroll
            for (int mt = 0; mt < 4; mt++) {
                uint32_t addr = sA + (uint32_t)((wm * 64 + mt * 16 + ga_row) * ASTR + k + ga_col) * 4;
                ldsm_x4(a[mt][0], a[mt][1], a[mt][2], a[mt][3], addr);
                a[mt][0] = tf32_round_u(a[mt][0]);
                a[mt][1] = tf32_round_u(a[mt][1]);
                a[mt][2] = tf32_round_u(a[mt][2]);
                a[mt][3] = tf32_round_u(a[mt][3]);
            }
            uint32_t b[4][2];
            #pragma unroll
            for (int nt = 0; nt < 4; nt++) {
                const float* bp = Bs + (k + t) * BSTR + wn * 32 + nt * 8 + g;
                b[nt][0] = tf32_round_u(__float_as_uint(bp[0]));
                b[nt][1] = tf32_round_u(__float_as_uint(bp[4 * BSTR]));
            }
            #pragma unroll
            for (int mt = 0; mt < 4; mt++)
                #pragma unroll
                for (int nt = 0; nt < 4; nt++)
                    mma_tf32(acc[mt][nt], a[mt], b[nt]);
        }
    }

    #pragma unroll
    for (int mt = 0; mt < 4; mt++) {
        #pragma unroll
        for (int nt = 0; nt < 4; nt++) {
            const int row = brow + wm * 64 + mt * 16 + g;
            const int col = n0 + wn * 32 + nt * 8 + 2 * t;
            float bx = 0.f, by = 0.f;
            if (HAS_BIAS) { bx = bias[col]; by = bias[col + 1]; }
            float2 v0 = make_float2(acc[mt][nt][0] + bx, acc[mt][nt][1] + by);
            float2 v1 = make_float2(acc[mt][nt][2] + bx, acc[mt][nt][3] + by);
            *(float2*)&C[(size_t)row * N + col]       = v0;
            *(float2*)&C[(size_t)(row + 8) * N + col] = v1;
        }
    }
}

// ===========================================================================
// Flash attention (causal, GQA rep=16), tf32 mma.sync + ldmatrix.
// BM=128 (8 warps), BN=64, 3-stage cp.async. S-prefetch pipeline: QK(kb+1)
// issues BEFORE softmax(kb)+PV(kb), so the tensor pipe stays busy during
// the softmax dependency chain.
// ===========================================================================
#define FBM 128
#define FBN 64
#define KSTR 132
#define VSTR2 68
#define K_FL (FBN * KSTR)            // 8448
#define V_FL (HEAD_DIM * VSTR2)      // 8704
#define FSTAGE_FL (K_FL + V_FL)      // 17152
#define FSMEM_BYTES (3 * FSTAGE_FL * 4)   // 205824

__global__ __launch_bounds__(256, 1) void flash_tc(float* __restrict__ out)
{
    extern __shared__ float fs[];
    const uint32_t sbase = smem_u32(fs);

    const int tid  = threadIdx.x;
    const int warp = tid >> 5;
    const int lane = tid & 31;
    const int g    = lane >> 2;
    const int t    = lane & 3;
    const int h    = blockIdx.y;
    const int kvh  = h / REP;
    const int qi   = gridDim.x - 1 - blockIdx.x;   // big blocks first
    const int q0   = qi * FBM;
    const int r0   = q0 + warp * 16 + g;
    const int r1   = r0 + 8;
    const float scale = 0.08838834764831845f;

    // ldmatrix lane mappings
    const int kq_row = (lane & 7) + ((lane >> 4) << 3);   // key offset 0..15
    const int kq_dim = ((lane >> 3) & 1) << 2;            // 0 or 4
    const int pv_dim = (lane & 7) + ((lane >> 4) << 3);   // dim offset 0..15
    const int pv_key = ((lane >> 3) & 1) << 2;            // 0 or 4

    // ---- Q fragments, pre-scaled + tf32-rounded, resident in registers ----
    uint32_t qa[16][4];
    {
        const float* qb = g_qkv + (size_t)(q0 + warp * 16) * QKV_OUT + h * HEAD_DIM;
        #pragma unroll
        for (int ks = 0; ks < 16; ks++) {
            qa[ks][0] = __float_as_uint(tf32_round(qb[(size_t)g       * QKV_OUT + ks * 8 + t]     * scale));
            qa[ks][1] = __float_as_uint(tf32_round(qb[(size_t)(g + 8) * QKV_OUT + ks * 8 + t]     * scale));
            qa[ks][2] = __float_as_uint(tf32_round(qb[(size_t)g       * QKV_OUT + ks * 8 + t + 4] * scale));
            qa[ks][3] = __float_as_uint(tf32_round(qb[(size_t)(g + 8) * QKV_OUT + ks * 8 + t + 4] * scale));
        }
    }

    auto load_kv = [&](int s, int kb) {
        const uint32_t sK = sbase + (uint32_t)s * (FSTAGE_FL * 4);
        const uint32_t sV = sK + K_FL * 4;
        const float* ksrc = g_qkv + (size_t)(kb * FBN) * QKV_OUT + NQ + kvh * HEAD_DIM;
        const float* vsrc = g_vt + (size_t)(kvh * HEAD_DIM) * SEQLEN + kb * FBN;
        #pragma unroll
        for (int p = 0; p < 8; p++) {
            int id = tid + p * 256;
            int r = id >> 5;             // key 0..63
            int c = (id & 31) << 2;      // dim 0..124
            cp_async16(sK + (uint32_t)(r * KSTR + c) * 4, ksrc + (size_t)r * QKV_OUT + c);
        }
        #pragma unroll
        for (int p = 0; p < 8; p++) {
            int id = tid + p * 256;
            int r = id >> 4;             // dim 0..127
            int c = (id & 15) << 2;      // key 0..60
            cp_async16(sV + (uint32_t)(r * VSTR2 + c) * 4, vsrc + (size_t)r * SEQLEN + c);
        }
    };

    // QK for one k-block: 128 HMMA into sc
    auto compute_qk = [&](float (&sc)[8][4], uint32_t sKu) {
        #pragma unroll
        for (int j = 0; j < 8; j++)
            #pragma unroll
            for (int q = 0; q < 4; q++) sc[j][q] = 0.0f;
        #pragma unroll
        for (int ks = 0; ks < 16; ks++) {
            #pragma unroll
            for (int jp = 0; jp < 4; jp++) {
                uint32_t b0, b1, b2, b3;
                uint32_t addr = sKu + (uint32_t)((jp * 16 + kq_row) * KSTR + ks * 8 + kq_dim) * 4;
                ldsm_x4(b0, b1, b2, b3, addr);
                uint32_t bb0[2] = { b0, b1 };
                uint32_t bb1[2] = { b2, b3 };
                mma_tf32(sc[2 * jp],     qa[ks], bb0);
                mma_tf32(sc[2 * jp + 1], qa[ks], bb1);
            }
        }
    };

    float o[16][4];
    #pragma unroll
    for (int d = 0; d < 16; d++)
        #pragma unroll
        for (int q = 0; q < 4; q++) o[d][q] = 0.0f;
    float m0 = -1e30f, m1 = -1e30f, l0 = 0.0f, l1 = 0.0f;

    const int nkb = (q0 + FBM) / FBN;    // >= 2
    load_kv(0, 0); CP_COMMIT();
    load_kv(1, 1); CP_COMMIT();

    const int srcA = (lane & ~3) | (t >> 1);
    const int srcB = srcA + 2;
    const int selo = t & 1;

    float sc_cur[8][4], sc_next[8][4];

    // prologue: tile 0 ready (pending {0,1}, wait<=1 ensures group 0)
    CP_WAIT1();
    __syncthreads();
    compute_qk(sc_cur, sbase);

    for (int kb = 0; kb < nkb; kb++) {
        // all pending loads (tile kb+1) complete; had a full iter of lead time
        CP_WAIT0();
        __syncthreads();
        if (kb + 2 < nkb) load_kv((kb + 2) % 3, kb + 2);
        CP_COMMIT();

        // ---- prefetch: S(kb+1) HMMAs issue now, drain during softmax(kb) ----
        if (kb + 1 < nkb)
            compute_qk(sc_next, sbase + (uint32_t)((kb + 1) % 3) * (FSTAGE_FL * 4));

        const uint32_t sVu = sbase + (uint32_t)(kb % 3) * (FSTAGE_FL * 4) + K_FL * 4;

        // ---- causal mask on current block ----
        if (kb >= nkb - 2) {
            const int keyb = kb * FBN + 2 * t;
            #pragma unroll
            for (int j = 0; j < 8; j++) {
                int k0 = keyb + j * 8;
                if (k0     > r0) sc_cur[j][0] = -1e30f;
                if (k0 + 1 > r0) sc_cur[j][1] = -1e30f;
                if (k0     > r1) sc_cur[j][2] = -1e30f;
                if (k0 + 1 > r1) sc_cur[j][3] = -1e30f;
            }
        }

        // ---- online softmax ----
        float mx0 = -1e30f, mx1 = -1e30f;
        #pragma unroll
        for (int j = 0; j < 8; j++) {
            mx0 = fmaxf(mx0, fmaxf(sc_cur[j][0], sc_cur[j][1]));
            mx1 = fmaxf(mx1, fmaxf(sc_cur[j][2], sc_cur[j][3]));
        }
        mx0 = fmaxf(mx0, __shfl_xor_sync(0xffffffffu, mx0, 1));
        mx0 = fmaxf(mx0, __shfl_xor_sync(0xffffffffu, mx0, 2));
        mx1 = fmaxf(mx1, __shfl_xor_sync(0xffffffffu, mx1, 1));
        mx1 = fmaxf(mx1, __shfl_xor_sync(0xffffffffu, mx1, 2));
        const float mn0 = fmaxf(m0, mx0);
        const float mn1 = fmaxf(m1, mx1);
        const float c0 = __expf(m0 - mn0);
        const float c1 = __expf(m1 - mn1);
        m0 = mn0; m1 = mn1;
        l0 *= c0;  l1 *= c1;
        #pragma unroll
        for (int d = 0; d < 16; d++) {
            o[d][0] *= c0; o[d][1] *= c0;
            o[d][2] *= c1; o[d][3] *= c1;
        }

        uint32_t pc[8][4];
        #pragma unroll
        for (int j = 0; j < 8; j++) {
            float p0 = __expf(sc_cur[j][0] - m0);
            float p1 = __expf(sc_cur[j][1] - m0);
            float p2 = __expf(sc_cur[j][2] - m1);
            float p3 = __expf(sc_cur[j][3] - m1);
            l0 += p0 + p1;
            l1 += p2 + p3;
            pc[j][0] = __float_as_uint(tf32_round(p0));
            pc[j][1] = __float_as_uint(tf32_round(p1));
            pc[j][2] = __float_as_uint(tf32_round(p2));
            pc[j][3] = __float_as_uint(tf32_round(p3));
        }

        // ---- O += P V; A-frag via quad shuffles, B-frag via ldmatrix.x4 ----
        #pragma unroll
        for (int j = 0; j < 8; j++) {
            uint32_t a[4];
            uint32_t x0 = __shfl_sync(0xffffffffu, pc[j][0], srcA);
            uint32_t x1 = __shfl_sync(0xffffffffu, pc[j][1], srcA);
            uint32_t x2 = __shfl_sync(0xffffffffu, pc[j][2], srcA);
            uint32_t x3 = __shfl_sync(0xffffffffu, pc[j][3], srcA);
            a[0] = selo ? x1 : x0;
            a[1] = selo ? x3 : x2;
            uint32_t y0 = __shfl_sync(0xffffffffu, pc[j][0], srcB);
            uint32_t y1 = __shfl_sync(0xffffffffu, pc[j][1], srcB);
            uint32_t y2 = __shfl_sync(0xffffffffu, pc[j][2], srcB);
            uint32_t y3 = __shfl_sync(0xffffffffu, pc[j][3], srcB);
            a[2] = selo ? y1 : y0;
            a[3] = selo ? y3 : y2;

            #pragma unroll
            for (int dp = 0; dp < 8; dp++) {
                uint32_t v0, v1, v2, v3;
                uint32_t addr = sVu + (uint32_t)((dp * 16 + pv_dim) * VSTR2 + j * 8 + pv_key) * 4;
                ldsm_x4(v0, v1, v2, v3, addr);
                uint32_t bb0[2] = { v0, v1 };
                uint32_t bb1[2] = { v2, v3 };
                mma_tf32(o[2 * dp],     a, bb0);
                mma_tf32(o[2 * dp + 1], a, bb1);
            }
        }

        // rotate S buffers
        #pragma unroll
        for (int j = 0; j < 8; j++)
            #pragma unroll
            for (int q = 0; q < 4; q++) sc_cur[j][q] = sc_next[j][q];
    }

    // ---- finalize ----
    l0 += __shfl_xor_sync(0xffffffffu, l0, 1);
    l0 += __shfl_xor_sync(0xffffffffu, l0, 2);
    l1 += __shfl_xor_sync(0xffffffffu, l1, 1);
    l1 += __shfl_xor_sync(0xffffffffu, l1, 2);
    const float inv0 = 1.0f / l0;
    const float inv1 = 1.0f / l1;

    float* op0 = out + (size_t)r0 * NQ + h * HEAD_DIM + 2 * t;
    float* op1 = out + (size_t)r1 * NQ + h * HEAD_DIM + 2 * t;
    #pragma unroll
    for (int d = 0; d < 16; d++) {
        float2 v0 = make_float2(tf32_round(o[d][0] * inv0), tf32_round(o[d][1] * inv0));
        float2 v1 = make_float2(tf32_round(o[d][2] * inv1), tf32_round(o[d][3] * inv1));
        *(float2*)(op0 + d * 8) = v0;
        *(float2*)(op1 + d * 8) = v1;
    }
}

// ---------------------------------------------------------------------------
// Launch
// ---------------------------------------------------------------------------
extern "C" void kernel_launch(void* const* d_in, const int* in_sizes, int n_in,
                              void* d_out, int out_size)
{
    const float* hidden = (const float*)d_in[0];
    const float* cosb   = (const float*)d_in[1];
    const float* sinb   = (const float*)d_in[2];
    const float* w_qkv  = (const float*)d_in[3];
    const float* b_qkv  = (const float*)d_in[4];
    const float* w_o    = (const float*)d_in[5];
    float* out = (float*)d_out;

    float *qkv = nullptr, *attn = nullptr;
    cudaGetSymbolAddress((void**)&qkv,  g_qkv);
    cudaGetSymbolAddress((void**)&attn, g_attn);

    cudaFuncSetAttribute(gemm_mma<true>,  cudaFuncAttributeMaxDynamicSharedMemorySize, GSMEM_BYTES);
    cudaFuncSetAttribute(gemm_mma<false>, cudaFuncAttributeMaxDynamicSharedMemorySize, GSMEM_BYTES);
    cudaFuncSetAttribute(flash_tc,        cudaFuncAttributeMaxDynamicSharedMemorySize, FSMEM_BYTES);

    // 1) QKV projection + bias (tf32 mma.sync; in-register tf32 rounding)
    gemm_mma<true><<<dim3(QKV_OUT / 128, SEQLEN / 128), 256, GSMEM_BYTES>>>(
        hidden, w_qkv, b_qkv, qkv, HIDDEN, QKV_OUT, QKV_OUT);

    // 2) fused RoPE + tf32-round + dim-major V copy
    {
        int total = SEQLEN * (QKV_OUT / 2);
        rope_round_kernel<<<(total + 255) / 256, 256>>>(cosb, sinb);
    }

    // 3) causal GQA flash attention on tensor cores (S-prefetch pipeline)
    flash_tc<<<dim3(SEQLEN / FBM, NUM_HEADS), 256, FSMEM_BYTES>>>(attn);

    // 4) output projection (tf32 mma.sync; in-register tf32 rounding)
    gemm_mma<false><<<dim3(HIDDEN / 128, SEQLEN / 128), 256, GSMEM_BYTES>>>(
        attn, w_o, nullptr, out, NQ, HIDDEN, HIDDEN);
}

// round 11
// speedup vs baseline: 1.1573x; 1.1573x over previous
#include <cuda_runtime.h>
#include <cstdint>
#include <math.h>

#define SEQLEN   2048
#define HIDDEN   4096
#define NUM_HEADS 32
#define NUM_KV_HEADS 2
#define HEAD_DIM 128
#define QKV_OUT  ((NUM_HEADS + 2 * NUM_KV_HEADS) * HEAD_DIM)   // 4608
#define NQ       (NUM_HEADS * HEAD_DIM)                        // 4096
#define NKV      (NUM_KV_HEADS * HEAD_DIM)                     // 256
#define REP      (NUM_HEADS / NUM_KV_HEADS)                    // 16

// Scratch (device globals; no allocation allowed in kernel_launch)
__device__ float g_qkv[SEQLEN * QKV_OUT];        // ~37.7 MB
__device__ float g_attn[SEQLEN * NQ];            // ~33.5 MB
__device__ float g_Ar[SEQLEN * HIDDEN];          // 32 MB  (tf32-rounded A)
__device__ float g_Br[HIDDEN * QKV_OUT];         // 72 MB  (tf32-rounded B)
__device__ float g_vt[NUM_KV_HEADS * HEAD_DIM * SEQLEN];  // 2 MB, V dim-major

// ===========================================================================
// helpers
// ===========================================================================
__device__ __forceinline__ float tf32_round(float f) {
    uint32_t u;
    asm("cvt.rna.tf32.f32 %0, %1;" : "=r"(u) : "f"(f));
    return __uint_as_float(u);
}
__device__ __forceinline__ uint32_t smem_u32(const void* p) {
    uint32_t a;
    asm("{ .reg .u64 t; cvta.to.shared.u64 t, %1; cvt.u32.u64 %0, t; }"
        : "=r"(a) : "l"(p));
    return a;
}
__device__ __forceinline__ void cp_async16(uint32_t dst, const void* src) {
    asm volatile("cp.async.cg.shared.global [%0], [%1], 16;" :: "r"(dst), "l"(src));
}
#define CP_COMMIT() asm volatile("cp.async.commit_group;" ::: "memory")
#define CP_WAIT1()  asm volatile("cp.async.wait_group 1;" ::: "memory")
#define CP_WAIT0()  asm volatile("cp.async.wait_group 0;" ::: "memory")

__device__ __forceinline__ void mma_tf32(float* c, const uint32_t* a, const uint32_t* b) {
    asm volatile(
        "mma.sync.aligned.m16n8k8.row.col.f32.tf32.tf32.f32 "
        "{%0,%1,%2,%3}, {%4,%5,%6,%7}, {%8,%9}, {%0,%1,%2,%3};"
        : "+f"(c[0]), "+f"(c[1]), "+f"(c[2]), "+f"(c[3])
        : "r"(a[0]), "r"(a[1]), "r"(a[2]), "r"(a[3]), "r"(b[0]), "r"(b[1]));
}
__device__ __forceinline__ void ldsm_x4(uint32_t& r0, uint32_t& r1,
                                        uint32_t& r2, uint32_t& r3, uint32_t addr) {
    asm volatile("ldmatrix.sync.aligned.m8n8.x4.shared.b16 {%0,%1,%2,%3}, [%4];"
        : "=r"(r0), "=r"(r1), "=r"(r2), "=r"(r3) : "r"(addr));
}

// ===========================================================================
// elementwise tf32 rounding pass (float4 vectorized; in-place allowed)
// ===========================================================================
__global__ void round_tf32_kernel(const float* __restrict__ in,
                                  float* __restrict__ out, int n4)
{
    int i = blockIdx.x * blockDim.x + threadIdx.x;
    if (i >= n4) return;
    float4 v = ((const float4*)in)[i];
    v.x = tf32_round(v.x); v.y = tf32_round(v.y);
    v.z = tf32_round(v.z); v.w = tf32_round(v.w);
    ((float4*)out)[i] = v;
}

// ===========================================================================
// Fused RoPE + tf32 rounding of qkv (in place) + dim-major V copy to g_vt.
// ===========================================================================
__global__ void rope_round_kernel(const float* __restrict__ cosb,
                                  const float* __restrict__ sinb)
{
    const int HALF = QKV_OUT / 2;
    int idx = blockIdx.x * blockDim.x + threadIdx.x;
    if (idx >= SEQLEN * HALF) return;
    int s = idx / HALF;
    int c = (idx - s * HALF) * 2;
    float2* p = (float2*)(g_qkv + (size_t)s * QKV_OUT + c);
    float2 v = *p;
    int head = c >> 7, dim = c & 127;
    if (head < NUM_HEADS + NUM_KV_HEADS && dim < 64) {
        int pair = dim >> 1;
        float cs = cosb[s * 64 + pair];
        float sn = sinb[s * 64 + pair];
        float x0 = v.x, x1 = v.y;
        v.x = x0 * cs - x1 * sn;
        v.y = x1 * cs + x0 * sn;
    }
    v.x = tf32_round(v.x);
    v.y = tf32_round(v.y);
    *p = v;
    if (head >= NUM_HEADS + NUM_KV_HEADS) {   // V heads -> dim-major copy
        int kvh = head - (NUM_HEADS + NUM_KV_HEADS);
        g_vt[((size_t)(kvh * HEAD_DIM + dim))     * SEQLEN + s] = v.x;
        g_vt[((size_t)(kvh * HEAD_DIM + dim + 1)) * SEQLEN + s] = v.y;
    }
}

// ===========================================================================
// tf32 mma.sync GEMM: C[M,N] = A[M,K] @ B[K,N] (+bias)
// Inputs must be pre-rounded to tf32. (R8 version — at HMMA roofline.)
// ===========================================================================
#define ASTR 36
#define BSTR 136
#define A_FL (128 * ASTR)
#define B_FL (32 * BSTR)
#define STAGE_FL (A_FL + B_FL)
#define GSMEM_BYTES (3 * STAGE_FL * 4)

template <bool HAS_BIAS>
__global__ __launch_bounds__(256)
void gemm_mma(const float* __restrict__ A, const float* __restrict__ B,
              const float* __restrict__ bias, float* __restrict__ C,
              int K, int ldb, int N)
{
    extern __shared__ float smem[];
    const uint32_t sbase = smem_u32(smem);

    const int tid  = threadIdx.x;
    const int warp = tid >> 5;
    const int lane = tid & 31;
    const int g    = lane >> 2;
    const int t    = lane & 3;
    const int wm   = warp & 1;
    const int wn   = warp >> 1;
    const int brow = blockIdx.y * 128;
    const int n0   = blockIdx.x * 128;

    const int ga_row = lane & 15;
    const int ga_col = (lane >> 4) << 2;

    auto load_stage = [&](int s, int k0) {
        const float* Ap = A + (size_t)brow * K + k0;
        const float* Bp = B + (size_t)k0 * ldb + n0;
        const uint32_t sA = sbase + (uint32_t)s * (STAGE_FL * 4);
        const uint32_t sB = sA + A_FL * 4;
        #pragma unroll
        for (int p = 0; p < 4; p++) {
            int id = tid + p * 256;
            int r = id >> 3, c = (id & 7) << 2;
            cp_async16(sA + (uint32_t)(r * ASTR + c) * 4, Ap + (size_t)r * K + c);
        }
        #pragma unroll
        for (int p = 0; p < 4; p++) {
            int id = tid + p * 256;
            int r = id >> 5, c = (id & 31) << 2;
            cp_async16(sB + (uint32_t)(r * BSTR + c) * 4, Bp + (size_t)r * ldb + c);
        }
    };

    const int iters = K / 32;
    load_stage(0, 0);  CP_COMMIT();
    load_stage(1, 32); CP_COMMIT();

    float acc[4][4][4];
    #pragma unroll
    for (int mt = 0; mt < 4; mt++)
        #pragma unroll
        for (int nt = 0; nt < 4; nt++)
            #pragma unroll
            for (int q = 0; q < 4; q++) acc[mt][nt][q] = 0.0f;

    for (int i = 0; i < iters; i++) {
        CP_WAIT1();
        __syncthreads();
        if (i + 2 < iters) load_stage((i + 2) % 3, (i + 2) * 32);
        CP_COMMIT();

        const uint32_t sA = sbase + (uint32_t)(i % 3) * (STAGE_FL * 4);
        const float* Bs = smem + (i % 3) * STAGE_FL + A_FL;

        #pragma unroll
        for (int kk = 0; kk < 4; kk++) {
            const int k = kk * 8;
            uint32_t a[4][4];
            #pragma unroll
            for (int mt = 0; mt < 4; mt++) {
                uint32_t addr = sA + (uint32_t)((wm * 64 + mt * 16 + ga_row) * ASTR + k + ga_col) * 4;
                ldsm_x4(a[mt][0], a[mt][1], a[mt][2], a[mt][3], addr);
            }
            uint32_t b[4][2];
            #pragma unroll
            for (int nt = 0; nt < 4; nt++) {
                const float* bp = Bs + (k + t) * BSTR + wn * 32 + nt * 8 + g;
                b[nt][0] = __float_as_uint(bp[0]);
                b[nt][1] = __float_as_uint(bp[4 * BSTR]);
            }
            #pragma unroll
            for (int mt = 0; mt < 4; mt++)
                #pragma unroll
                for (int nt = 0; nt < 4; nt++)
                    mma_tf32(acc[mt][nt], a[mt], b[nt]);
        }
    }

    #pragma unroll
    for (int mt = 0; mt < 4; mt++) {
        #pragma unroll
        for (int nt = 0; nt < 4; nt++) {
            const int row = brow + wm * 64 + mt * 16 + g;
            const int col = n0 + wn * 32 + nt * 8 + 2 * t;
            float bx = 0.f, by = 0.f;
            if (HAS_BIAS) { bx = bias[col]; by = bias[col + 1]; }
            float2 v0 = make_float2(acc[mt][nt][0] + bx, acc[mt][nt][1] + by);
            float2 v1 = make_float2(acc[mt][nt][2] + bx, acc[mt][nt][3] + by);
            *(float2*)&C[(size_t)row * N + col]       = v0;
            *(float2*)&C[(size_t)(row + 8) * N + col] = v1;
        }
    }
}

// ===========================================================================
// Flash attention (causal, GQA rep=16), tf32 mma.sync + ldmatrix.
// BM=128 (8 warps), BN=64, 3-stage cp.async. S-prefetch pipeline: QK(kb+1)
// issues BEFORE softmax(kb)+PV(kb), keeping the tensor pipe busy during the
// softmax dependency chain.  (R10 version — measured ~180 us.)
// ===========================================================================
#define FBM 128
#define FBN 64
#define KSTR 132
#define VSTR2 68
#define K_FL (FBN * KSTR)            // 8448
#define V_FL (HEAD_DIM * VSTR2)      // 8704
#define FSTAGE_FL (K_FL + V_FL)      // 17152
#define FSMEM_BYTES (3 * FSTAGE_FL * 4)   // 205824

__global__ __launch_bounds__(256, 1) void flash_tc(float* __restrict__ out)
{
    extern __shared__ float fs[];
    const uint32_t sbase = smem_u32(fs);

    const int tid  = threadIdx.x;
    const int warp = tid >> 5;
    const int lane = tid & 31;
    const int g    = lane >> 2;
    const int t    = lane & 3;
    const int h    = blockIdx.y;
    const int kvh  = h / REP;
    const int qi   = gridDim.x - 1 - blockIdx.x;   // big blocks first
    const int q0   = qi * FBM;
    const int r0   = q0 + warp * 16 + g;
    const int r1   = r0 + 8;
    const float scale = 0.08838834764831845f;

    const int kq_row = (lane & 7) + ((lane >> 4) << 3);
    const int kq_dim = ((lane >> 3) & 1) << 2;
    const int pv_dim = (lane & 7) + ((lane >> 4) << 3);
    const int pv_key = ((lane >> 3) & 1) << 2;

    uint32_t qa[16][4];
    {
        const float* qb = g_qkv + (size_t)(q0 + warp * 16) * QKV_OUT + h * HEAD_DIM;
        #pragma unroll
        for (int ks = 0; ks < 16; ks++) {
            qa[ks][0] = __float_as_uint(tf32_round(qb[(size_t)g       * QKV_OUT + ks * 8 + t]     * scale));
            qa[ks][1] = __float_as_uint(tf32_round(qb[(size_t)(g + 8) * QKV_OUT + ks * 8 + t]     * scale));
            qa[ks][2] = __float_as_uint(tf32_round(qb[(size_t)g       * QKV_OUT + ks * 8 + t + 4] * scale));
            qa[ks][3] = __float_as_uint(tf32_round(qb[(size_t)(g + 8) * QKV_OUT + ks * 8 + t + 4] * scale));
        }
    }

    auto load_kv = [&](int s, int kb) {
        const uint32_t sK = sbase + (uint32_t)s * (FSTAGE_FL * 4);
        const uint32_t sV = sK + K_FL * 4;
        const float* ksrc = g_qkv + (size_t)(kb * FBN) * QKV_OUT + NQ + kvh * HEAD_DIM;
        const float* vsrc = g_vt + (size_t)(kvh * HEAD_DIM) * SEQLEN + kb * FBN;
        #pragma unroll
        for (int p = 0; p < 8; p++) {
            int id = tid + p * 256;
            int r = id >> 5;
            int c = (id & 31) << 2;
            cp_async16(sK + (uint32_t)(r * KSTR + c) * 4, ksrc + (size_t)r * QKV_OUT + c);
        }
        #pragma unroll
        for (int p = 0; p < 8; p++) {
            int id = tid + p * 256;
            int r = id >> 4;
            int c = (id & 15) << 2;
            cp_async16(sV + (uint32_t)(r * VSTR2 + c) * 4, vsrc + (size_t)r * SEQLEN + c);
        }
    };

    auto compute_qk = [&](float (&sc)[8][4], uint32_t sKu) {
        #pragma unroll
        for (int j = 0; j < 8; j++)
            #pragma unroll
            for (int q = 0; q < 4; q++) sc[j][q] = 0.0f;
        #pragma unroll
        for (int ks = 0; ks < 16; ks++) {
            #pragma unroll
            for (int jp = 0; jp < 4; jp++) {
                uint32_t b0, b1, b2, b3;
                uint32_t addr = sKu + (uint32_t)((jp * 16 + kq_row) * KSTR + ks * 8 + kq_dim) * 4;
                ldsm_x4(b0, b1, b2, b3, addr);
                uint32_t bb0[2] = { b0, b1 };
                uint32_t bb1[2] = { b2, b3 };
                mma_tf32(sc[2 * jp],     qa[ks], bb0);
                mma_tf32(sc[2 * jp + 1], qa[ks], bb1);
            }
        }
    };

    float o[16][4];
    #pragma unroll
    for (int d = 0; d < 16; d++)
        #pragma unroll
        for (int q = 0; q < 4; q++) o[d][q] = 0.0f;
    float m0 = -1e30f, m1 = -1e30f, l0 = 0.0f, l1 = 0.0f;

    const int nkb = (q0 + FBM) / FBN;    // >= 2
    load_kv(0, 0); CP_COMMIT();
    load_kv(1, 1); CP_COMMIT();

    const int srcA = (lane & ~3) | (t >> 1);
    const int srcB = srcA + 2;
    const int selo = t & 1;

    float sc_cur[8][4], sc_next[8][4];

    CP_WAIT1();
    __syncthreads();
    compute_qk(sc_cur, sbase);

    for (int kb = 0; kb < nkb; kb++) {
        CP_WAIT0();
        __syncthreads();
        if (kb + 2 < nkb) load_kv((kb + 2) % 3, kb + 2);
        CP_COMMIT();

        if (kb + 1 < nkb)
            compute_qk(sc_next, sbase + (uint32_t)((kb + 1) % 3) * (FSTAGE_FL * 4));

        const uint32_t sVu = sbase + (uint32_t)(kb % 3) * (FSTAGE_FL * 4) + K_FL * 4;

        if (kb >= nkb - 2) {
            const int keyb = kb * FBN + 2 * t;
            #pragma unroll
            for (int j = 0; j < 8; j++) {
                int k0 = keyb + j * 8;
                if (k0     > r0) sc_cur[j][0] = -1e30f;
                if (k0 + 1 > r0) sc_cur[j][1] = -1e30f;
                if (k0     > r1) sc_cur[j][2] = -1e30f;
                if (k0 + 1 > r1) sc_cur[j][3] = -1e30f;
            }
        }

        float mx0 = -1e30f, mx1 = -1e30f;
        #pragma unroll
        for (int j = 0; j < 8; j++) {
            mx0 = fmaxf(mx0, fmaxf(sc_cur[j][0], sc_cur[j][1]));
            mx1 = fmaxf(mx1, fmaxf(sc_cur[j][2], sc_cur[j][3]));
        }
        mx0 = fmaxf(mx0, __shfl_xor_sync(0xffffffffu, mx0, 1));
        mx0 = fmaxf(mx0, __shfl_xor_sync(0xffffffffu, mx0, 2));
        mx1 = fmaxf(mx1, __shfl_xor_sync(0xffffffffu, mx1, 1));
        mx1 = fmaxf(mx1, __shfl_xor_sync(0xffffffffu, mx1, 2));
        const float mn0 = fmaxf(m0, mx0);
        const float mn1 = fmaxf(m1, mx1);
        const float c0 = __expf(m0 - mn0);
        const float c1 = __expf(m1 - mn1);
        m0 = mn0; m1 = mn1;
        l0 *= c0;  l1 *= c1;
        #pragma unroll
        for (int d = 0; d < 16; d++) {
            o[d][0] *= c0; o[d][1] *= c0;
            o[d][2] *= c1; o[d][3] *= c1;
        }

        uint32_t pc[8][4];
        #pragma unroll
        for (int j = 0; j < 8; j++) {
            float p0 = __expf(sc_cur[j][0] - m0);
            float p1 = __expf(sc_cur[j][1] - m0);
            float p2 = __expf(sc_cur[j][2] - m1);
            float p3 = __expf(sc_cur[j][3] - m1);
            l0 += p0 + p1;
            l1 += p2 + p3;
            pc[j][0] = __float_as_uint(tf32_round(p0));
            pc[j][1] = __float_as_uint(tf32_round(p1));
            pc[j][2] = __float_as_uint(tf32_round(p2));
            pc[j][3] = __float_as_uint(tf32_round(p3));
        }

        #pragma unroll
        for (int j = 0; j < 8; j++) {
            uint32_t a[4];
            uint32_t x0 = __shfl_sync(0xffffffffu, pc[j][0], srcA);
            uint32_t x1 = __shfl_sync(0xffffffffu, pc[j][1], srcA);
            uint32_t x2 = __shfl_sync(0xffffffffu, pc[j][2], srcA);
            uint32_t x3 = __shfl_sync(0xffffffffu, pc[j][3], srcA);
            a[0] = selo ? x1 : x0;
            a[1] = selo ? x3 : x2;
            uint32_t y0 = __shfl_sync(0xffffffffu, pc[j][0], srcB);
            uint32_t y1 = __shfl_sync(0xffffffffu, pc[j][1], srcB);
            uint32_t y2 = __shfl_sync(0xffffffffu, pc[j][2], srcB);
            uint32_t y3 = __shfl_sync(0xffffffffu, pc[j][3], srcB);
            a[2] = selo ? y1 : y0;
            a[3] = selo ? y3 : y2;

            #pragma unroll
            for (int dp = 0; dp < 8; dp++) {
                uint32_t v0, v1, v2, v3;
                uint32_t addr = sVu + (uint32_t)((dp * 16 + pv_dim) * VSTR2 + j * 8 + pv_key) * 4;
                ldsm_x4(v0, v1, v2, v3, addr);
                uint32_t bb0[2] = { v0, v1 };
                uint32_t bb1[2] = { v2, v3 };
                mma_tf32(o[2 * dp],     a, bb0);
                mma_tf32(o[2 * dp + 1], a, bb1);
            }
        }

        #pragma unroll
        for (int j = 0; j < 8; j++)
            #pragma unroll
            for (int q = 0; q < 4; q++) sc_cur[j][q] = sc_next[j][q];
    }

    l0 += __shfl_xor_sync(0xffffffffu, l0, 1);
    l0 += __shfl_xor_sync(0xffffffffu, l0, 2);
    l1 += __shfl_xor_sync(0xffffffffu, l1, 1);
    l1 += __shfl_xor_sync(0xffffffffu, l1, 2);
    const float inv0 = 1.0f / l0;
    const float inv1 = 1.0f / l1;

    float* op0 = out + (size_t)r0 * NQ + h * HEAD_DIM + 2 * t;
    float* op1 = out + (size_t)r1 * NQ + h * HEAD_DIM + 2 * t;
    #pragma unroll
    for (int d = 0; d < 16; d++) {
        float2 v0 = make_float2(tf32_round(o[d][0] * inv0), tf32_round(o[d][1] * inv0));
        float2 v1 = make_float2(tf32_round(o[d][2] * inv1), tf32_round(o[d][3] * inv1));
        *(float2*)(op0 + d * 8) = v0;
        *(float2*)(op1 + d * 8) = v1;
    }
}

// ---------------------------------------------------------------------------
// Launch
// ---------------------------------------------------------------------------
extern "C" void kernel_launch(void* const* d_in, const int* in_sizes, int n_in,
                              void* d_out, int out_size)
{
    const float* hidden = (const float*)d_in[0];
    const float* cosb   = (const float*)d_in[1];
    const float* sinb   = (const float*)d_in[2];
    const float* w_qkv  = (const float*)d_in[3];
    const float* b_qkv  = (const float*)d_in[4];
    const float* w_o    = (const float*)d_in[5];
    float* out = (float*)d_out;

    float *qkv = nullptr, *attn = nullptr, *Ar = nullptr, *Br = nullptr;
    cudaGetSymbolAddress((void**)&qkv,  g_qkv);
    cudaGetSymbolAddress((void**)&attn, g_attn);
    cudaGetSymbolAddress((void**)&Ar,   g_Ar);
    cudaGetSymbolAddress((void**)&Br,   g_Br);

    cudaFuncSetAttribute(gemm_mma<true>,  cudaFuncAttributeMaxDynamicSharedMemorySize, GSMEM_BYTES);
    cudaFuncSetAttribute(gemm_mma<false>, cudaFuncAttributeMaxDynamicSharedMemorySize, GSMEM_BYTES);
    cudaFuncSetAttribute(flash_tc,        cudaFuncAttributeMaxDynamicSharedMemorySize, FSMEM_BYTES);

    // 0) tf32-round GEMM1 operands
    {
        int n4 = SEQLEN * HIDDEN / 4;
        round_tf32_kernel<<<(n4 + 255) / 256, 256>>>(hidden, Ar, n4);
        n4 = HIDDEN * QKV_OUT / 4;
        round_tf32_kernel<<<(n4 + 255) / 256, 256>>>(w_qkv, Br, n4);
    }

    // 1) QKV projection + bias (tf32 mma.sync, pre-rounded operands)
    gemm_mma<true><<<dim3(QKV_OUT / 128, SEQLEN / 128), 256, GSMEM_BYTES>>>(
        Ar, Br, b_qkv, qkv, HIDDEN, QKV_OUT, QKV_OUT);

    // 2) fused RoPE + tf32-round + dim-major V copy
    {
        int total = SEQLEN * (QKV_OUT / 2);
        rope_round_kernel<<<(total + 255) / 256, 256>>>(cosb, sinb);
    }

    // 3) causal GQA flash attention on tensor cores (S-prefetch pipeline)
    flash_tc<<<dim3(SEQLEN / FBM, NUM_HEADS), 256, FSMEM_BYTES>>>(attn);

    // 4) tf32-round w_o (stream-ordered after GEMM1: safe to reuse Br)
    {
        int n4 = NQ * HIDDEN / 4;
        round_tf32_kernel<<<(n4 + 255) / 256, 256>>>(w_o, Br, n4);
    }

    // 5) output projection (tf32 mma.sync, pre-rounded operands)
    gemm_mma<false><<<dim3(HIDDEN / 128, SEQLEN / 128), 256, GSMEM_BYTES>>>(
        attn, Br, nullptr, out, NQ, HIDDEN, HIDDEN);
}

// round 13
// speedup vs baseline: 1.9956x; 1.7244x over previous
#include <cuda_runtime.h>
#include <cuda_fp16.h>
#include <cstdint>
#include <math.h>

#define SEQLEN   2048
#define HIDDEN   4096
#define NUM_HEADS 32
#define NUM_KV_HEADS 2
#define HEAD_DIM 128
#define QKV_OUT  ((NUM_HEADS + 2 * NUM_KV_HEADS) * HEAD_DIM)   // 4608
#define NQ       (NUM_HEADS * HEAD_DIM)                        // 4096
#define NKV      (NUM_KV_HEADS * HEAD_DIM)                     // 256
#define REP      (NUM_HEADS / NUM_KV_HEADS)                    // 16

// Scratch (device globals)
__device__ float  g_qkv[SEQLEN * QKV_OUT];        // fp32 GEMM1 out
__device__ __half g_qkvh[SEQLEN * QKV_OUT];       // fp16 roped qkv (Q pre-scaled)
__device__ __half g_attnh[SEQLEN * NQ];           // fp16 attention out
__device__ __half g_Ah[SEQLEN * HIDDEN];          // fp16 hidden
__device__ __half g_Bh[HIDDEN * QKV_OUT];         // fp16 weights (reused for w_o)
__device__ __half g_vth[NUM_KV_HEADS * HEAD_DIM * SEQLEN];  // fp16 V dim-major

// ===========================================================================
// helpers
// ===========================================================================
__device__ __forceinline__ uint32_t smem_u32(const void* p) {
    uint32_t a;
    asm("{ .reg .u64 t; cvta.to.shared.u64 t, %1; cvt.u32.u64 %0, t; }"
        : "=r"(a) : "l"(p));
    return a;
}
__device__ __forceinline__ void cp_async16(uint32_t dst, const void* src) {
    asm volatile("cp.async.cg.shared.global [%0], [%1], 16;" :: "r"(dst), "l"(src));
}
#define CP_COMMIT() asm volatile("cp.async.commit_group;" ::: "memory")
#define CP_WAIT1()  asm volatile("cp.async.wait_group 1;" ::: "memory")

__device__ __forceinline__ void mma_f16(float* c, const uint32_t* a, const uint32_t* b) {
    asm volatile(
        "mma.sync.aligned.m16n8k16.row.col.f32.f16.f16.f32 "
        "{%0,%1,%2,%3}, {%4,%5,%6,%7}, {%8,%9}, {%0,%1,%2,%3};"
        : "+f"(c[0]), "+f"(c[1]), "+f"(c[2]), "+f"(c[3])
        : "r"(a[0]), "r"(a[1]), "r"(a[2]), "r"(a[3]), "r"(b[0]), "r"(b[1]));
}
__device__ __forceinline__ void ldsm_x4(uint32_t& r0, uint32_t& r1,
                                        uint32_t& r2, uint32_t& r3, uint32_t addr) {
    asm volatile("ldmatrix.sync.aligned.m8n8.x4.shared.b16 {%0,%1,%2,%3}, [%4];"
        : "=r"(r0), "=r"(r1), "=r"(r2), "=r"(r3) : "r"(addr));
}
__device__ __forceinline__ void ldsm_x4_t(uint32_t& r0, uint32_t& r1,
                                          uint32_t& r2, uint32_t& r3, uint32_t addr) {
    asm volatile("ldmatrix.sync.aligned.m8n8.x4.trans.shared.b16 {%0,%1,%2,%3}, [%4];"
        : "=r"(r0), "=r"(r1), "=r"(r2), "=r"(r3) : "r"(addr));
}
// pack {lo, hi} floats -> f16x2 register
__device__ __forceinline__ uint32_t pack_h2(float lo, float hi) {
    uint32_t r;
    asm("cvt.rn.f16x2.f32 %0, %1, %2;" : "=r"(r) : "f"(hi), "f"(lo));
    return r;
}

// ===========================================================================
// fp32 -> fp16 conversion pass (4 elems/thread)
// ===========================================================================
__global__ void cvt_half_kernel(const float* __restrict__ in,
                                __half* __restrict__ out, int n4)
{
    int i = blockIdx.x * blockDim.x + threadIdx.x;
    if (i >= n4) return;
    float4 v = ((const float4*)in)[i];
    uint2 o;
    o.x = pack_h2(v.x, v.y);
    o.y = pack_h2(v.z, v.w);
    ((uint2*)out)[i] = o;
}

// ===========================================================================
// Fused RoPE + fp16 conversion (Q pre-scaled by 1/sqrt(hd)) + dim-major V.
// ===========================================================================
__global__ void rope_half_kernel(const float* __restrict__ cosb,
                                 const float* __restrict__ sinb)
{
    const int HALF = QKV_OUT / 2;
    int idx = blockIdx.x * blockDim.x + threadIdx.x;
    if (idx >= SEQLEN * HALF) return;
    int s = idx / HALF;
    int c = (idx - s * HALF) * 2;
    float2 v = *(const float2*)(g_qkv + (size_t)s * QKV_OUT + c);
    int head = c >> 7, dim = c & 127;
    if (head < NUM_HEADS + NUM_KV_HEADS && dim < 64) {
        int pair = dim >> 1;
        float cs = cosb[s * 64 + pair];
        float sn = sinb[s * 64 + pair];
        float x0 = v.x, x1 = v.y;
        v.x = x0 * cs - x1 * sn;
        v.y = x1 * cs + x0 * sn;
    }
    if (head < NUM_HEADS) {   // pre-scale Q
        v.x *= 0.08838834764831845f;
        v.y *= 0.08838834764831845f;
    }
    *(uint32_t*)(g_qkvh + (size_t)s * QKV_OUT + c) = pack_h2(v.x, v.y);
    if (head >= NUM_HEADS + NUM_KV_HEADS) {   // V -> dim-major fp16
        int kvh = head - (NUM_HEADS + NUM_KV_HEADS);
        g_vth[((size_t)(kvh * HEAD_DIM + dim))     * SEQLEN + s] = __float2half_rn(v.x);
        g_vth[((size_t)(kvh * HEAD_DIM + dim + 1)) * SEQLEN + s] = __float2half_rn(v.y);
    }
}

// ===========================================================================
// fp16 mma.sync GEMM: C[M,N](fp32) = A[M,K] @ B[K,N] (+bias)
// CTA 128x128, BK=32, 8 warps (2x4) warp-tile 64x32, 3-stage cp.async.
// A smem [128][40] halves (ldsm non-trans), B smem [32][136] halves
// (ldsm.trans). All fragment LDSM patterns conflict-free.
// ===========================================================================
#define ASTRH 40
#define BSTRH 136
#define A_ST_B (128 * ASTRH * 2)           // 10240
#define B_ST_B (32 * BSTRH * 2)            // 8704
#define STAGE_B (A_ST_B + B_ST_B)          // 18944
#define GSMEM_BYTES (3 * STAGE_B)          // 56832

template <bool HAS_BIAS>
__global__ __launch_bounds__(256)
void gemm_f16(const __half* __restrict__ A, const __half* __restrict__ B,
              const float* __restrict__ bias, float* __restrict__ C,
              int K, int ldb, int N)
{
    extern __shared__ char smem[];
    const uint32_t sbase = smem_u32(smem);

    const int tid  = threadIdx.x;
    const int warp = tid >> 5;
    const int lane = tid & 31;
    const int g    = lane >> 2;
    const int t    = lane & 3;
    const int wm   = warp & 1;
    const int wn   = warp >> 1;
    const int brow = blockIdx.y * 128;
    const int n0   = blockIdx.x * 128;

    // ldmatrix lane mappings
    const int a_row = lane & 15;                 // A: row within 16
    const int a_col = (lane >> 4) << 3;          // A: col 0/8
    const int b_krow = (lane & 7) + (((lane >> 3) & 1) << 3);  // B: k-row 0..15
    const int b_ncol = (lane >> 4) << 3;                        // B: n col 0/8

    auto load_stage = [&](int s, int k0) {
        const __half* Ap = A + (size_t)brow * K + k0;
        const __half* Bp = B + (size_t)k0 * ldb + n0;
        const uint32_t sA = sbase + (uint32_t)s * STAGE_B;
        const uint32_t sB = sA + A_ST_B;
        #pragma unroll
        for (int p = 0; p < 2; p++) {
            int id = tid + p * 256;              // 512 chunks: A 128 rows x 4
            int r = id >> 2, c = (id & 3) << 3;
            cp_async16(sA + (uint32_t)(r * ASTRH + c) * 2, Ap + (size_t)r * K + c);
        }
        #pragma unroll
        for (int p = 0; p < 2; p++) {
            int id = tid + p * 256;              // 512 chunks: B 32 rows x 16
            int r = id >> 4, c = (id & 15) << 3;
            cp_async16(sB + (uint32_t)(r * BSTRH + c) * 2, Bp + (size_t)r * ldb + c);
        }
    };

    const int iters = K / 32;
    load_stage(0, 0);  CP_COMMIT();
    load_stage(1, 32); CP_COMMIT();

    float acc[4][4][4];
    #pragma unroll
    for (int mt = 0; mt < 4; mt++)
        #pragma unroll
        for (int nt = 0; nt < 4; nt++)
            #pragma unroll
            for (int q = 0; q < 4; q++) acc[mt][nt][q] = 0.0f;

    for (int i = 0; i < iters; i++) {
        CP_WAIT1();
        __syncthreads();
        if (i + 2 < iters) load_stage((i + 2) % 3, (i + 2) * 32);
        CP_COMMIT();

        const uint32_t sA = sbase + (uint32_t)(i % 3) * STAGE_B;
        const uint32_t sB = sA + A_ST_B;

        #pragma unroll
        for (int kk = 0; kk < 2; kk++) {           // two k16 steps
            uint32_t a[4][4];
            #pragma unroll
            for (int mt = 0; mt < 4; mt++) {
                uint32_t addr = sA + (uint32_t)((wm * 64 + mt * 16 + a_row) * ASTRH
                                                + kk * 16 + a_col) * 2;
                ldsm_x4(a[mt][0], a[mt][1], a[mt][2], a[mt][3], addr);
            }
            uint32_t b[4][2];
            #pragma unroll
            for (int np = 0; np < 2; np++) {       // pairs of n8-tiles
                uint32_t r0, r1, r2, r3;
                uint32_t addr = sB + (uint32_t)((kk * 16 + b_krow) * BSTRH
                                                + wn * 32 + np * 16 + b_ncol) * 2;
                ldsm_x4_t(r0, r1, r2, r3, addr);
                b[np * 2][0] = r0; b[np * 2][1] = r1;
                b[np * 2 + 1][0] = r2; b[np * 2 + 1][1] = r3;
            }
            #pragma unroll
            for (int mt = 0; mt < 4; mt++)
                #pragma unroll
                for (int nt = 0; nt < 4; nt++)
                    mma_f16(acc[mt][nt], a[mt], b[nt]);
        }
    }

    #pragma unroll
    for (int mt = 0; mt < 4; mt++) {
        #pragma unroll
        for (int nt = 0; nt < 4; nt++) {
            const int row = brow + wm * 64 + mt * 16 + g;
            const int col = n0 + wn * 32 + nt * 8 + 2 * t;
            float bx = 0.f, by = 0.f;
            if (HAS_BIAS) { bx = bias[col]; by = bias[col + 1]; }
            float2 v0 = make_float2(acc[mt][nt][0] + bx, acc[mt][nt][1] + by);
            float2 v1 = make_float2(acc[mt][nt][2] + bx, acc[mt][nt][3] + by);
            *(float2*)&C[(size_t)row * N + col]       = v0;
            *(float2*)&C[(size_t)(row + 8) * N + col] = v1;
        }
    }
}

// ===========================================================================
// Flash attention (causal, GQA rep=16), fp16 mma.sync m16n8k16 + ldmatrix.
// BM=128 (8 warps), BN=64, 3-stage cp.async. P C-frag -> A-frag relayout is
// the identity under fp16 packing (no shuffles).
// ===========================================================================
#define FBM 128
#define FBN 64
#define KSTRH 136          // halves; 272B row stride == 4 banks mod 32
#define VSTRH 72           // halves; 144B row stride == 4 banks mod 32
#define K_ST_B (FBN * KSTRH * 2)          // 17408
#define V_ST_B (HEAD_DIM * VSTRH * 2)     // 18432
#define FSTG_B (K_ST_B + V_ST_B)          // 35840
#define FSMEM_BYTES (3 * FSTG_B)          // 107520

__global__ __launch_bounds__(256, 1) void flash_f16(__half* __restrict__ out)
{
    extern __shared__ char fsm[];
    const uint32_t sbase = smem_u32(fsm);

    const int tid  = threadIdx.x;
    const int warp = tid >> 5;
    const int lane = tid & 31;
    const int g    = lane >> 2;
    const int t    = lane & 3;
    const int h    = blockIdx.y;
    const int kvh  = h / REP;
    const int qi   = gridDim.x - 1 - blockIdx.x;   // big blocks first
    const int q0   = qi * FBM;
    const int r0   = q0 + warp * 16 + g;
    const int r1   = r0 + 8;

    // ldmatrix lane mappings
    const int kq_key = (lane & 7) + ((lane >> 4) << 3);
    const int kq_dim = ((lane >> 3) & 1) << 3;
    const int pv_dim = (lane & 7) + ((lane >> 4) << 3);
    const int pv_key = ((lane >> 3) & 1) << 3;

    // ---- Q fragments (fp16, pre-scaled by rope kernel) in registers ----
    uint32_t qa[8][4];
    {
        const __half* qb = g_qkvh + (size_t)(q0 + warp * 16) * QKV_OUT + h * HEAD_DIM;
        #pragma unroll
        for (int ks = 0; ks < 8; ks++) {
            qa[ks][0] = *(const uint32_t*)(qb + (size_t)g       * QKV_OUT + ks * 16 + 2 * t);
            qa[ks][1] = *(const uint32_t*)(qb + (size_t)(g + 8) * QKV_OUT + ks * 16 + 2 * t);
            qa[ks][2] = *(const uint32_t*)(qb + (size_t)g       * QKV_OUT + ks * 16 + 8 + 2 * t);
            qa[ks][3] = *(const uint32_t*)(qb + (size_t)(g + 8) * QKV_OUT + ks * 16 + 8 + 2 * t);
        }
    }

    auto load_kv = [&](int s, int kb) {
        const uint32_t sK = sbase + (uint32_t)s * FSTG_B;
        const uint32_t sV = sK + K_ST_B;
        const __half* ksrc = g_qkvh + (size_t)(kb * FBN) * QKV_OUT + NQ + kvh * HEAD_DIM;
        const __half* vsrc = g_vth + (size_t)(kvh * HEAD_DIM) * SEQLEN + kb * FBN;
        #pragma unroll
        for (int p = 0; p < 4; p++) {
            int id = tid + p * 256;                 // 1024: K 64 rows x 16 chunks
            int r = id >> 4, c = (id & 15) << 3;
            cp_async16(sK + (uint32_t)(r * KSTRH + c) * 2, ksrc + (size_t)r * QKV_OUT + c);
        }
        #pragma unroll
        for (int p = 0; p < 4; p++) {
            int id = tid + p * 256;                 // 1024: V 128 dims x 8 chunks
            int r = id >> 3, c = (id & 7) << 3;
            cp_async16(sV + (uint32_t)(r * VSTRH + c) * 2, vsrc + (size_t)r * SEQLEN + c);
        }
    };

    float o[16][4];
    #pragma unroll
    for (int d = 0; d < 16; d++)
        #pragma unroll
        for (int q = 0; q < 4; q++) o[d][q] = 0.0f;
    float m0 = -1e30f, m1 = -1e30f, l0 = 0.0f, l1 = 0.0f;

    const int nkb = (q0 + FBM) / FBN;
    load_kv(0, 0); CP_COMMIT();
    load_kv(1, 1); CP_COMMIT();

    for (int kb = 0; kb < nkb; kb++) {
        CP_WAIT1();
        __syncthreads();
        if (kb + 2 < nkb) load_kv((kb + 2) % 3, kb + 2);
        CP_COMMIT();

        const uint32_t sKu = sbase + (uint32_t)(kb % 3) * FSTG_B;
        const uint32_t sVu = sKu + K_ST_B;

        // ---- S = Q K^T ----
        float sc[8][4];
        #pragma unroll
        for (int j = 0; j < 8; j++)
            #pragma unroll
            for (int q = 0; q < 4; q++) sc[j][q] = 0.0f;

        #pragma unroll
        for (int ks = 0; ks < 8; ks++) {
            #pragma unroll
            for (int jp = 0; jp < 4; jp++) {
                uint32_t b0, b1, b2, b3;
                uint32_t addr = sKu + (uint32_t)((jp * 16 + kq_key) * KSTRH
                                                 + ks * 16 + kq_dim) * 2;
                ldsm_x4(b0, b1, b2, b3, addr);
                uint32_t bb0[2] = { b0, b1 };
                uint32_t bb1[2] = { b2, b3 };
                mma_f16(sc[2 * jp],     qa[ks], bb0);
                mma_f16(sc[2 * jp + 1], qa[ks], bb1);
            }
        }

        // ---- causal mask (last two k-blocks only) ----
        if (kb >= nkb - 2) {
            const int keyb = kb * FBN + 2 * t;
            #pragma unroll
            for (int j = 0; j < 8; j++) {
                int k0 = keyb + j * 8;
                if (k0     > r0) sc[j][0] = -1e30f;
                if (k0 + 1 > r0) sc[j][1] = -1e30f;
                if (k0     > r1) sc[j][2] = -1e30f;
                if (k0 + 1 > r1) sc[j][3] = -1e30f;
            }
        }

        // ---- online softmax ----
        float mx0 = -1e30f, mx1 = -1e30f;
        #pragma unroll
        for (int j = 0; j < 8; j++) {
            mx0 = fmaxf(mx0, fmaxf(sc[j][0], sc[j][1]));
            mx1 = fmaxf(mx1, fmaxf(sc[j][2], sc[j][3]));
        }
        mx0 = fmaxf(mx0, __shfl_xor_sync(0xffffffffu, mx0, 1));
        mx0 = fmaxf(mx0, __shfl_xor_sync(0xffffffffu, mx0, 2));
        mx1 = fmaxf(mx1, __shfl_xor_sync(0xffffffffu, mx1, 1));
        mx1 = fmaxf(mx1, __shfl_xor_sync(0xffffffffu, mx1, 2));
        const float mn0 = fmaxf(m0, mx0);
        const float mn1 = fmaxf(m1, mx1);
        const float c0 = __expf(m0 - mn0);
        const float c1 = __expf(m1 - mn1);
        m0 = mn0; m1 = mn1;
        l0 *= c0;  l1 *= c1;
        #pragma unroll
        for (int d = 0; d < 16; d++) {
            o[d][0] *= c0; o[d][1] *= c0;
            o[d][2] *= c1; o[d][3] *= c1;
        }

        // ---- P = exp(S - m), pack straight into fp16 A-fragments ----
        uint32_t pa[4][4];     // [key16-chunk][frag]
        #pragma unroll
        for (int jj = 0; jj < 4; jj++) {
            float p00 = __expf(sc[2*jj][0]   - m0);
            float p01 = __expf(sc[2*jj][1]   - m0);
            float p02 = __expf(sc[2*jj][2]   - m1);
            float p03 = __expf(sc[2*jj][3]   - m1);
            float p10 = __expf(sc[2*jj+1][0] - m0);
            float p11 = __expf(sc[2*jj+1][1] - m0);
            float p12 = __expf(sc[2*jj+1][2] - m1);
            float p13 = __expf(sc[2*jj+1][3] - m1);
            l0 += p00 + p01 + p10 + p11;
            l1 += p02 + p03 + p12 + p13;
            pa[jj][0] = pack_h2(p00, p01);
            pa[jj][1] = pack_h2(p02, p03);
            pa[jj][2] = pack_h2(p10, p11);
            pa[jj][3] = pack_h2(p12, p13);
        }

        // ---- O += P V ----
        #pragma unroll
        for (int jj = 0; jj < 4; jj++) {
            #pragma unroll
            for (int dp = 0; dp < 8; dp++) {
                uint32_t v0, v1, v2, v3;
                uint32_t addr = sVu + (uint32_t)((dp * 16 + pv_dim) * VSTRH
                                                 + jj * 16 + pv_key) * 2;
                ldsm_x4(v0, v1, v2, v3, addr);
                uint32_t bb0[2] = { v0, v1 };
                uint32_t bb1[2] = { v2, v3 };
                mma_f16(o[2 * dp],     pa[jj], bb0);
                mma_f16(o[2 * dp + 1], pa[jj], bb1);
            }
        }
    }

    // ---- finalize ----
    l0 += __shfl_xor_sync(0xffffffffu, l0, 1);
    l0 += __shfl_xor_sync(0xffffffffu, l0, 2);
    l1 += __shfl_xor_sync(0xffffffffu, l1, 1);
    l1 += __shfl_xor_sync(0xffffffffu, l1, 2);
    const float inv0 = 1.0f / l0;
    const float inv1 = 1.0f / l1;

    __half* op0 = out + (size_t)r0 * NQ + h * HEAD_DIM + 2 * t;
    __half* op1 = out + (size_t)r1 * NQ + h * HEAD_DIM + 2 * t;
    #pragma unroll
    for (int d = 0; d < 16; d++) {
        *(uint32_t*)(op0 + d * 8) = pack_h2(o[d][0] * inv0, o[d][1] * inv0);
        *(uint32_t*)(op1 + d * 8) = pack_h2(o[d][2] * inv1, o[d][3] * inv1);
    }
}

// ---------------------------------------------------------------------------
// Launch
// ---------------------------------------------------------------------------
extern "C" void kernel_launch(void* const* d_in, const int* in_sizes, int n_in,
                              void* d_out, int out_size)
{
    const float* hidden = (const float*)d_in[0];
    const float* cosb   = (const float*)d_in[1];
    const float* sinb   = (const float*)d_in[2];
    const float* w_qkv  = (const float*)d_in[3];
    const float* b_qkv  = (const float*)d_in[4];
    const float* w_o    = (const float*)d_in[5];
    float* out = (float*)d_out;

    float* qkv = nullptr;
    __half *Ah = nullptr, *Bh = nullptr, *attnh = nullptr;
    cudaGetSymbolAddress((void**)&qkv,   g_qkv);
    cudaGetSymbolAddress((void**)&Ah,    g_Ah);
    cudaGetSymbolAddress((void**)&Bh,    g_Bh);
    cudaGetSymbolAddress((void**)&attnh, g_attnh);

    cudaFuncSetAttribute(gemm_f16<true>,  cudaFuncAttributeMaxDynamicSharedMemorySize, GSMEM_BYTES);
    cudaFuncSetAttribute(gemm_f16<false>, cudaFuncAttributeMaxDynamicSharedMemorySize, GSMEM_BYTES);
    cudaFuncSetAttribute(flash_f16,       cudaFuncAttributeMaxDynamicSharedMemorySize, FSMEM_BYTES);

    // 0) fp16 conversion of GEMM1 operands
    {
        int n4 = SEQLEN * HIDDEN / 4;
        cvt_half_kernel<<<(n4 + 255) / 256, 256>>>(hidden, Ah, n4);
        n4 = HIDDEN * QKV_OUT / 4;
        cvt_half_kernel<<<(n4 + 255) / 256, 256>>>(w_qkv, Bh, n4);
    }

    // 1) QKV projection + bias (fp16 mma, fp32 accum/out)
    gemm_f16<true><<<dim3(QKV_OUT / 128, SEQLEN / 128), 256, GSMEM_BYTES>>>(
        Ah, Bh, b_qkv, qkv, HIDDEN, QKV_OUT, QKV_OUT);

    // 2) fused RoPE + fp16 conversion + dim-major V
    {
        int total = SEQLEN * (QKV_OUT / 2);
        rope_half_kernel<<<(total + 255) / 256, 256>>>(cosb, sinb);
    }

    // 3) causal GQA flash attention (fp16 mma)
    flash_f16<<<dim3(SEQLEN / FBM, NUM_HEADS), 256, FSMEM_BYTES>>>(attnh);

    // 4) fp16 conversion of w_o (after GEMM1: safe to reuse Bh)
    {
        int n4 = NQ * HIDDEN / 4;
        cvt_half_kernel<<<(n4 + 255) / 256, 256>>>(w_o, Bh, n4);
    }

    // 5) output projection (fp16 mma, fp32 accum/out)
    gemm_f16<false><<<dim3(HIDDEN / 128, SEQLEN / 128), 256, GSMEM_BYTES>>>(
        attnh, Bh, nullptr, out, NQ, HIDDEN, HIDDEN);
}

// round 14
// speedup vs baseline: 2.0545x; 1.0295x over previous
#include <cuda_runtime.h>
#include <cuda_fp16.h>
#include <cstdint>
#include <math.h>

#define SEQLEN   2048
#define HIDDEN   4096
#define NUM_HEADS 32
#define NUM_KV_HEADS 2
#define HEAD_DIM 128
#define QKV_OUT  ((NUM_HEADS + 2 * NUM_KV_HEADS) * HEAD_DIM)   // 4608
#define NQ       (NUM_HEADS * HEAD_DIM)                        // 4096
#define NKV      (NUM_KV_HEADS * HEAD_DIM)                     // 256
#define REP      (NUM_HEADS / NUM_KV_HEADS)                    // 16

// Scratch (device globals)
__device__ __half g_qkvh[SEQLEN * QKV_OUT];       // fp16 roped qkv (Q pre-scaled)
__device__ __half g_attnh[SEQLEN * NQ];           // fp16 attention out
__device__ __half g_Ah[SEQLEN * HIDDEN];          // fp16 hidden
__device__ __half g_Bh[HIDDEN * QKV_OUT];         // fp16 weights (reused for w_o)
__device__ __half g_vth[NUM_KV_HEADS * HEAD_DIM * SEQLEN];  // fp16 V dim-major

// ===========================================================================
// helpers
// ===========================================================================
__device__ __forceinline__ uint32_t smem_u32(const void* p) {
    uint32_t a;
    asm("{ .reg .u64 t; cvta.to.shared.u64 t, %1; cvt.u32.u64 %0, t; }"
        : "=r"(a) : "l"(p));
    return a;
}
__device__ __forceinline__ void cp_async16(uint32_t dst, const void* src) {
    asm volatile("cp.async.cg.shared.global [%0], [%1], 16;" :: "r"(dst), "l"(src));
}
#define CP_COMMIT() asm volatile("cp.async.commit_group;" ::: "memory")
#define CP_WAIT1()  asm volatile("cp.async.wait_group 1;" ::: "memory")

__device__ __forceinline__ void mma_f16(float* c, const uint32_t* a, const uint32_t* b) {
    asm volatile(
        "mma.sync.aligned.m16n8k16.row.col.f32.f16.f16.f32 "
        "{%0,%1,%2,%3}, {%4,%5,%6,%7}, {%8,%9}, {%0,%1,%2,%3};"
        : "+f"(c[0]), "+f"(c[1]), "+f"(c[2]), "+f"(c[3])
        : "r"(a[0]), "r"(a[1]), "r"(a[2]), "r"(a[3]), "r"(b[0]), "r"(b[1]));
}
__device__ __forceinline__ void ldsm_x4(uint32_t& r0, uint32_t& r1,
                                        uint32_t& r2, uint32_t& r3, uint32_t addr) {
    asm volatile("ldmatrix.sync.aligned.m8n8.x4.shared.b16 {%0,%1,%2,%3}, [%4];"
        : "=r"(r0), "=r"(r1), "=r"(r2), "=r"(r3) : "r"(addr));
}
__device__ __forceinline__ void ldsm_x4_t(uint32_t& r0, uint32_t& r1,
                                          uint32_t& r2, uint32_t& r3, uint32_t addr) {
    asm volatile("ldmatrix.sync.aligned.m8n8.x4.trans.shared.b16 {%0,%1,%2,%3}, [%4];"
        : "=r"(r0), "=r"(r1), "=r"(r2), "=r"(r3) : "r"(addr));
}
// pack {lo, hi} floats -> f16x2 register
__device__ __forceinline__ uint32_t pack_h2(float lo, float hi) {
    uint32_t r;
    asm("cvt.rn.f16x2.f32 %0, %1, %2;" : "=r"(r) : "f"(hi), "f"(lo));
    return r;
}

// ===========================================================================
// fp32 -> fp16 conversion pass (8 elems/thread, MLP=2)
// ===========================================================================
__global__ void cvt_half_kernel(const float* __restrict__ in,
                                __half* __restrict__ out, int n8)
{
    int i = blockIdx.x * blockDim.x + threadIdx.x;
    if (i >= n8) return;
    float4 a = ((const float4*)in)[2 * i];
    float4 b = ((const float4*)in)[2 * i + 1];
    uint4 o;
    o.x = pack_h2(a.x, a.y);
    o.y = pack_h2(a.z, a.w);
    o.z = pack_h2(b.x, b.y);
    o.w = pack_h2(b.z, b.w);
    ((uint4*)out)[i] = o;
}

// ===========================================================================
// fp16 mma.sync GEMM core + two epilogues:
//  - QKV variant: +bias, RoPE (interleaved rot=64), Q pre-scale, fp16 pack to
//    g_qkvh, and dim-major V scatter to g_vth. No fp32 intermediate at all.
//  - plain variant: +optional bias, fp32 out.
// CTA 128x128, BK=32, 8 warps (2x4) warp-tile 64x32, 3-stage cp.async.
// ===========================================================================
#define ASTRH 40
#define BSTRH 136
#define A_ST_B (128 * ASTRH * 2)           // 10240
#define B_ST_B (32 * BSTRH * 2)            // 8704
#define STAGE_B (A_ST_B + B_ST_B)          // 18944
#define GSMEM_BYTES (3 * STAGE_B)          // 56832

template <int EPI>   // 0 = plain fp32 out, 1 = fused QKV epilogue
__global__ __launch_bounds__(256)
void gemm_f16(const __half* __restrict__ A, const __half* __restrict__ B,
              const float* __restrict__ bias, float* __restrict__ C,
              const float* __restrict__ cosb, const float* __restrict__ sinb,
              int K, int ldb, int N)
{
    extern __shared__ char smem[];
    const uint32_t sbase = smem_u32(smem);

    const int tid  = threadIdx.x;
    const int warp = tid >> 5;
    const int lane = tid & 31;
    const int g    = lane >> 2;
    const int t    = lane & 3;
    const int wm   = warp & 1;
    const int wn   = warp >> 1;
    const int brow = blockIdx.y * 128;
    const int n0   = blockIdx.x * 128;

    const int a_row = lane & 15;
    const int a_col = (lane >> 4) << 3;
    const int b_krow = (lane & 7) + (((lane >> 3) & 1) << 3);
    const int b_ncol = (lane >> 4) << 3;

    auto load_stage = [&](int s, int k0) {
        const __half* Ap = A + (size_t)brow * K + k0;
        const __half* Bp = B + (size_t)k0 * ldb + n0;
        const uint32_t sA = sbase + (uint32_t)s * STAGE_B;
        const uint32_t sB = sA + A_ST_B;
        #pragma unroll
        for (int p = 0; p < 2; p++) {
            int id = tid + p * 256;
            int r = id >> 2, c = (id & 3) << 3;
            cp_async16(sA + (uint32_t)(r * ASTRH + c) * 2, Ap + (size_t)r * K + c);
        }
        #pragma unroll
        for (int p = 0; p < 2; p++) {
            int id = tid + p * 256;
            int r = id >> 4, c = (id & 15) << 3;
            cp_async16(sB + (uint32_t)(r * BSTRH + c) * 2, Bp + (size_t)r * ldb + c);
        }
    };

    const int iters = K / 32;
    load_stage(0, 0);  CP_COMMIT();
    load_stage(1, 32); CP_COMMIT();

    float acc[4][4][4];
    #pragma unroll
    for (int mt = 0; mt < 4; mt++)
        #pragma unroll
        for (int nt = 0; nt < 4; nt++)
            #pragma unroll
            for (int q = 0; q < 4; q++) acc[mt][nt][q] = 0.0f;

    for (int i = 0; i < iters; i++) {
        CP_WAIT1();
        __syncthreads();
        if (i + 2 < iters) load_stage((i + 2) % 3, (i + 2) * 32);
        CP_COMMIT();

        const uint32_t sA = sbase + (uint32_t)(i % 3) * STAGE_B;
        const uint32_t sB = sA + A_ST_B;

        #pragma unroll
        for (int kk = 0; kk < 2; kk++) {
            uint32_t a[4][4];
            #pragma unroll
            for (int mt = 0; mt < 4; mt++) {
                uint32_t addr = sA + (uint32_t)((wm * 64 + mt * 16 + a_row) * ASTRH
                                                + kk * 16 + a_col) * 2;
                ldsm_x4(a[mt][0], a[mt][1], a[mt][2], a[mt][3], addr);
            }
            uint32_t b[4][2];
            #pragma unroll
            for (int np = 0; np < 2; np++) {
                uint32_t r0, r1, r2, r3;
                uint32_t addr = sB + (uint32_t)((kk * 16 + b_krow) * BSTRH
                                                + wn * 32 + np * 16 + b_ncol) * 2;
                ldsm_x4_t(r0, r1, r2, r3, addr);
                b[np * 2][0] = r0; b[np * 2][1] = r1;
                b[np * 2 + 1][0] = r2; b[np * 2 + 1][1] = r3;
            }
            #pragma unroll
            for (int mt = 0; mt < 4; mt++)
                #pragma unroll
                for (int nt = 0; nt < 4; nt++)
                    mma_f16(acc[mt][nt], a[mt], b[nt]);
        }
    }

    if (EPI == 0) {
        #pragma unroll
        for (int mt = 0; mt < 4; mt++) {
            #pragma unroll
            for (int nt = 0; nt < 4; nt++) {
                const int row = brow + wm * 64 + mt * 16 + g;
                const int col = n0 + wn * 32 + nt * 8 + 2 * t;
                float bx = 0.f, by = 0.f;
                if (bias) { bx = bias[col]; by = bias[col + 1]; }
                float2 v0 = make_float2(acc[mt][nt][0] + bx, acc[mt][nt][1] + by);
                float2 v1 = make_float2(acc[mt][nt][2] + bx, acc[mt][nt][3] + by);
                *(float2*)&C[(size_t)row * N + col]       = v0;
                *(float2*)&C[(size_t)(row + 8) * N + col] = v1;
            }
        }
    } else {
        // ---- fused QKV epilogue: bias + RoPE + scale + fp16 + V transpose ----
        const float scale = 0.08838834764831845f;
        #pragma unroll
        for (int nt = 0; nt < 4; nt++) {
            const int col  = n0 + wn * 32 + nt * 8 + 2 * t;
            const int head = col >> 7;
            const int dim  = col & 127;
            const bool do_rope  = (dim < 64);   // heads 0..33 all have rot dims; head 34,35 are V
            const bool is_q     = (head < NUM_HEADS);
            const bool is_v     = (head >= NUM_HEADS + NUM_KV_HEADS);
            const float bx = bias[col];
            const float by = bias[col + 1];
            #pragma unroll
            for (int mt = 0; mt < 4; mt++) {
                const int row0 = brow + wm * 64 + mt * 16 + g;
                #pragma unroll
                for (int rr = 0; rr < 2; rr++) {
                    const int row = row0 + rr * 8;
                    float x = acc[mt][nt][2 * rr]     + bx;
                    float y = acc[mt][nt][2 * rr + 1] + by;
                    if (!is_v && do_rope) {
                        float cs = cosb[row * 64 + (dim >> 1)];
                        float sn = sinb[row * 64 + (dim >> 1)];
                        float x0 = x, x1 = y;
                        x = x0 * cs - x1 * sn;
                        y = x1 * cs + x0 * sn;
                    }
                    if (is_q) { x *= scale; y *= scale; }
                    *(uint32_t*)(g_qkvh + (size_t)row * QKV_OUT + col) = pack_h2(x, y);
                    if (is_v) {
                        int kvh = head - (NUM_HEADS + NUM_KV_HEADS);
                        g_vth[((size_t)(kvh * HEAD_DIM + dim))     * SEQLEN + row] = __float2half_rn(x);
                        g_vth[((size_t)(kvh * HEAD_DIM + dim + 1)) * SEQLEN + row] = __float2half_rn(y);
                    }
                }
            }
        }
    }
}

// ===========================================================================
// Flash attention (causal, GQA rep=16), fp16 mma.sync m16n8k16 + ldmatrix.
// BM=128 (8 warps), BN=64, 3-stage cp.async. (unchanged from R13)
// ===========================================================================
#define FBM 128
#define FBN 64
#define KSTRH 136
#define VSTRH 72
#define K_ST_B (FBN * KSTRH * 2)
#define V_ST_B (HEAD_DIM * VSTRH * 2)
#define FSTG_B (K_ST_B + V_ST_B)
#define FSMEM_BYTES (3 * FSTG_B)

__global__ __launch_bounds__(256, 1) void flash_f16(__half* __restrict__ out)
{
    extern __shared__ char fsm[];
    const uint32_t sbase = smem_u32(fsm);

    const int tid  = threadIdx.x;
    const int warp = tid >> 5;
    const int lane = tid & 31;
    const int g    = lane >> 2;
    const int t    = lane & 3;
    const int h    = blockIdx.y;
    const int kvh  = h / REP;
    const int qi   = gridDim.x - 1 - blockIdx.x;
    const int q0   = qi * FBM;
    const int r0   = q0 + warp * 16 + g;
    const int r1   = r0 + 8;

    const int kq_key = (lane & 7) + ((lane >> 4) << 3);
    const int kq_dim = ((lane >> 3) & 1) << 3;
    const int pv_dim = (lane & 7) + ((lane >> 4) << 3);
    const int pv_key = ((lane >> 3) & 1) << 3;

    uint32_t qa[8][4];
    {
        const __half* qb = g_qkvh + (size_t)(q0 + warp * 16) * QKV_OUT + h * HEAD_DIM;
        #pragma unroll
        for (int ks = 0; ks < 8; ks++) {
            qa[ks][0] = *(const uint32_t*)(qb + (size_t)g       * QKV_OUT + ks * 16 + 2 * t);
            qa[ks][1] = *(const uint32_t*)(qb + (size_t)(g + 8) * QKV_OUT + ks * 16 + 2 * t);
            qa[ks][2] = *(const uint32_t*)(qb + (size_t)g       * QKV_OUT + ks * 16 + 8 + 2 * t);
            qa[ks][3] = *(const uint32_t*)(qb + (size_t)(g + 8) * QKV_OUT + ks * 16 + 8 + 2 * t);
        }
    }

    auto load_kv = [&](int s, int kb) {
        const uint32_t sK = sbase + (uint32_t)s * FSTG_B;
        const uint32_t sV = sK + K_ST_B;
        const __half* ksrc = g_qkvh + (size_t)(kb * FBN) * QKV_OUT + NQ + kvh * HEAD_DIM;
        const __half* vsrc = g_vth + (size_t)(kvh * HEAD_DIM) * SEQLEN + kb * FBN;
        #pragma unroll
        for (int p = 0; p < 4; p++) {
            int id = tid + p * 256;
            int r = id >> 4, c = (id & 15) << 3;
            cp_async16(sK + (uint32_t)(r * KSTRH + c) * 2, ksrc + (size_t)r * QKV_OUT + c);
        }
        #pragma unroll
        for (int p = 0; p < 4; p++) {
            int id = tid + p * 256;
            int r = id >> 3, c = (id & 7) << 3;
            cp_async16(sV + (uint32_t)(r * VSTRH + c) * 2, vsrc + (size_t)r * SEQLEN + c);
        }
    };

    float o[16][4];
    #pragma unroll
    for (int d = 0; d < 16; d++)
        #pragma unroll
        for (int q = 0; q < 4; q++) o[d][q] = 0.0f;
    float m0 = -1e30f, m1 = -1e30f, l0 = 0.0f, l1 = 0.0f;

    const int nkb = (q0 + FBM) / FBN;
    load_kv(0, 0); CP_COMMIT();
    load_kv(1, 1); CP_COMMIT();

    for (int kb = 0; kb < nkb; kb++) {
        CP_WAIT1();
        __syncthreads();
        if (kb + 2 < nkb) load_kv((kb + 2) % 3, kb + 2);
        CP_COMMIT();

        const uint32_t sKu = sbase + (uint32_t)(kb % 3) * FSTG_B;
        const uint32_t sVu = sKu + K_ST_B;

        float sc[8][4];
        #pragma unroll
        for (int j = 0; j < 8; j++)
            #pragma unroll
            for (int q = 0; q < 4; q++) sc[j][q] = 0.0f;

        #pragma unroll
        for (int ks = 0; ks < 8; ks++) {
            #pragma unroll
            for (int jp = 0; jp < 4; jp++) {
                uint32_t b0, b1, b2, b3;
                uint32_t addr = sKu + (uint32_t)((jp * 16 + kq_key) * KSTRH
                                                 + ks * 16 + kq_dim) * 2;
                ldsm_x4(b0, b1, b2, b3, addr);
                uint32_t bb0[2] = { b0, b1 };
                uint32_t bb1[2] = { b2, b3 };
                mma_f16(sc[2 * jp],     qa[ks], bb0);
                mma_f16(sc[2 * jp + 1], qa[ks], bb1);
            }
        }

        if (kb >= nkb - 2) {
            const int keyb = kb * FBN + 2 * t;
            #pragma unroll
            for (int j = 0; j < 8; j++) {
                int k0 = keyb + j * 8;
                if (k0     > r0) sc[j][0] = -1e30f;
                if (k0 + 1 > r0) sc[j][1] = -1e30f;
                if (k0     > r1) sc[j][2] = -1e30f;
                if (k0 + 1 > r1) sc[j][3] = -1e30f;
            }
        }

        float mx0 = -1e30f, mx1 = -1e30f;
        #pragma unroll
        for (int j = 0; j < 8; j++) {
            mx0 = fmaxf(mx0, fmaxf(sc[j][0], sc[j][1]));
            mx1 = fmaxf(mx1, fmaxf(sc[j][2], sc[j][3]));
        }
        mx0 = fmaxf(mx0, __shfl_xor_sync(0xffffffffu, mx0, 1));
        mx0 = fmaxf(mx0, __shfl_xor_sync(0xffffffffu, mx0, 2));
        mx1 = fmaxf(mx1, __shfl_xor_sync(0xffffffffu, mx1, 1));
        mx1 = fmaxf(mx1, __shfl_xor_sync(0xffffffffu, mx1, 2));
        const float mn0 = fmaxf(m0, mx0);
        const float mn1 = fmaxf(m1, mx1);
        const float c0 = __expf(m0 - mn0);
        const float c1 = __expf(m1 - mn1);
        m0 = mn0; m1 = mn1;
        l0 *= c0;  l1 *= c1;
        #pragma unroll
        for (int d = 0; d < 16; d++) {
            o[d][0] *= c0; o[d][1] *= c0;
            o[d][2] *= c1; o[d][3] *= c1;
        }

        uint32_t pa[4][4];
        #pragma unroll
        for (int jj = 0; jj < 4; jj++) {
            float p00 = __expf(sc[2*jj][0]   - m0);
            float p01 = __expf(sc[2*jj][1]   - m0);
            float p02 = __expf(sc[2*jj][2]   - m1);
            float p03 = __expf(sc[2*jj][3]   - m1);
            float p10 = __expf(sc[2*jj+1][0] - m0);
            float p11 = __expf(sc[2*jj+1][1] - m0);
            float p12 = __expf(sc[2*jj+1][2] - m1);
            float p13 = __expf(sc[2*jj+1][3] - m1);
            l0 += p00 + p01 + p10 + p11;
            l1 += p02 + p03 + p12 + p13;
            pa[jj][0] = pack_h2(p00, p01);
            pa[jj][1] = pack_h2(p02, p03);
            pa[jj][2] = pack_h2(p10, p11);
            pa[jj][3] = pack_h2(p12, p13);
        }

        #pragma unroll
        for (int jj = 0; jj < 4; jj++) {
            #pragma unroll
            for (int dp = 0; dp < 8; dp++) {
                uint32_t v0, v1, v2, v3;
                uint32_t addr = sVu + (uint32_t)((dp * 16 + pv_dim) * VSTRH
                                                 + jj * 16 + pv_key) * 2;
                ldsm_x4(v0, v1, v2, v3, addr);
                uint32_t bb0[2] = { v0, v1 };
                uint32_t bb1[2] = { v2, v3 };
                mma_f16(o[2 * dp],     pa[jj], bb0);
                mma_f16(o[2 * dp + 1], pa[jj], bb1);
            }
        }
    }

    l0 += __shfl_xor_sync(0xffffffffu, l0, 1);
    l0 += __shfl_xor_sync(0xffffffffu, l0, 2);
    l1 += __shfl_xor_sync(0xffffffffu, l1, 1);
    l1 += __shfl_xor_sync(0xffffffffu, l1, 2);
    const float inv0 = 1.0f / l0;
    const float inv1 = 1.0f / l1;

    __half* op0 = out + (size_t)r0 * NQ + h * HEAD_DIM + 2 * t;
    __half* op1 = out + (size_t)r1 * NQ + h * HEAD_DIM + 2 * t;
    #pragma unroll
    for (int d = 0; d < 16; d++) {
        *(uint32_t*)(op0 + d * 8) = pack_h2(o[d][0] * inv0, o[d][1] * inv0);
        *(uint32_t*)(op1 + d * 8) = pack_h2(o[d][2] * inv1, o[d][3] * inv1);
    }
}

// ---------------------------------------------------------------------------
// Launch
// ---------------------------------------------------------------------------
extern "C" void kernel_launch(void* const* d_in, const int* in_sizes, int n_in,
                              void* d_out, int out_size)
{
    const float* hidden = (const float*)d_in[0];
    const float* cosb   = (const float*)d_in[1];
    const float* sinb   = (const float*)d_in[2];
    const float* w_qkv  = (const float*)d_in[3];
    const float* b_qkv  = (const float*)d_in[4];
    const float* w_o    = (const float*)d_in[5];
    float* out = (float*)d_out;

    __half *Ah = nullptr, *Bh = nullptr, *attnh = nullptr;
    cudaGetSymbolAddress((void**)&Ah,    g_Ah);
    cudaGetSymbolAddress((void**)&Bh,    g_Bh);
    cudaGetSymbolAddress((void**)&attnh, g_attnh);

    cudaFuncSetAttribute(gemm_f16<0>, cudaFuncAttributeMaxDynamicSharedMemorySize, GSMEM_BYTES);
    cudaFuncSetAttribute(gemm_f16<1>, cudaFuncAttributeMaxDynamicSharedMemorySize, GSMEM_BYTES);
    cudaFuncSetAttribute(flash_f16,   cudaFuncAttributeMaxDynamicSharedMemorySize, FSMEM_BYTES);

    // 0) fp16 conversion of GEMM1 operands
    {
        int n8 = SEQLEN * HIDDEN / 8;
        cvt_half_kernel<<<(n8 + 255) / 256, 256>>>(hidden, Ah, n8);
        n8 = HIDDEN * QKV_OUT / 8;
        cvt_half_kernel<<<(n8 + 255) / 256, 256>>>(w_qkv, Bh, n8);
    }

    // 1) QKV projection with FUSED bias+RoPE+scale+fp16+V-transpose epilogue
    gemm_f16<1><<<dim3(QKV_OUT / 128, SEQLEN / 128), 256, GSMEM_BYTES>>>(
        Ah, Bh, b_qkv, nullptr, cosb, sinb, HIDDEN, QKV_OUT, QKV_OUT);

    // 2) causal GQA flash attention (fp16 mma)
    flash_f16<<<dim3(SEQLEN / FBM, NUM_HEADS), 256, FSMEM_BYTES>>>(attnh);

    // 3) fp16 conversion of w_o (after GEMM1: safe to reuse Bh)
    {
        int n8 = NQ * HIDDEN / 8;
        cvt_half_kernel<<<(n8 + 255) / 256, 256>>>(w_o, Bh, n8);
    }

    // 4) output projection (fp16 mma, fp32 out)
    gemm_f16<0><<<dim3(HIDDEN / 128, SEQLEN / 128), 256, GSMEM_BYTES>>>(
        attnh, Bh, nullptr, out, nullptr, nullptr, NQ, HIDDEN, HIDDEN);
}

// round 15
// speedup vs baseline: 2.0640x; 1.0046x over previous
#include <cuda_runtime.h>
#include <cuda_fp16.h>
#include <cstdint>
#include <math.h>

#define SEQLEN   2048
#define HIDDEN   4096
#define NUM_HEADS 32
#define NUM_KV_HEADS 2
#define HEAD_DIM 128
#define QKV_OUT  ((NUM_HEADS + 2 * NUM_KV_HEADS) * HEAD_DIM)   // 4608
#define NQ       (NUM_HEADS * HEAD_DIM)                        // 4096
#define NKV      (NUM_KV_HEADS * HEAD_DIM)                     // 256
#define REP      (NUM_HEADS / NUM_KV_HEADS)                    // 16

// Scratch (device globals)
__device__ __half g_qkvh[SEQLEN * QKV_OUT];       // fp16 roped qkv (Q pre-scaled)
__device__ __half g_attnh[SEQLEN * NQ];           // fp16 attention out
__device__ __half g_Ah[SEQLEN * HIDDEN];          // fp16 hidden
__device__ __half g_Bh[HIDDEN * QKV_OUT];         // fp16 w_qkv
__device__ __half g_Wo[NQ * HIDDEN];              // fp16 w_o (converted inside flash launch)
__device__ __half g_vth[NUM_KV_HEADS * HEAD_DIM * SEQLEN];  // fp16 V dim-major

// ===========================================================================
// helpers
// ===========================================================================
__device__ __forceinline__ uint32_t smem_u32(const void* p) {
    uint32_t a;
    asm("{ .reg .u64 t; cvta.to.shared.u64 t, %1; cvt.u32.u64 %0, t; }"
        : "=r"(a) : "l"(p));
    return a;
}
__device__ __forceinline__ void cp_async16(uint32_t dst, const void* src) {
    asm volatile("cp.async.cg.shared.global [%0], [%1], 16;" :: "r"(dst), "l"(src));
}
#define CP_COMMIT() asm volatile("cp.async.commit_group;" ::: "memory")
#define CP_WAIT1()  asm volatile("cp.async.wait_group 1;" ::: "memory")

__device__ __forceinline__ void mma_f16(float* c, const uint32_t* a, const uint32_t* b) {
    asm volatile(
        "mma.sync.aligned.m16n8k16.row.col.f32.f16.f16.f32 "
        "{%0,%1,%2,%3}, {%4,%5,%6,%7}, {%8,%9}, {%0,%1,%2,%3};"
        : "+f"(c[0]), "+f"(c[1]), "+f"(c[2]), "+f"(c[3])
        : "r"(a[0]), "r"(a[1]), "r"(a[2]), "r"(a[3]), "r"(b[0]), "r"(b[1]));
}
__device__ __forceinline__ void ldsm_x4(uint32_t& r0, uint32_t& r1,
                                        uint32_t& r2, uint32_t& r3, uint32_t addr) {
    asm volatile("ldmatrix.sync.aligned.m8n8.x4.shared.b16 {%0,%1,%2,%3}, [%4];"
        : "=r"(r0), "=r"(r1), "=r"(r2), "=r"(r3) : "r"(addr));
}
__device__ __forceinline__ void ldsm_x4_t(uint32_t& r0, uint32_t& r1,
                                          uint32_t& r2, uint32_t& r3, uint32_t addr) {
    asm volatile("ldmatrix.sync.aligned.m8n8.x4.trans.shared.b16 {%0,%1,%2,%3}, [%4];"
        : "=r"(r0), "=r"(r1), "=r"(r2), "=r"(r3) : "r"(addr));
}
__device__ __forceinline__ uint32_t pack_h2(float lo, float hi) {
    uint32_t r;
    asm("cvt.rn.f16x2.f32 %0, %1, %2;" : "=r"(r) : "f"(hi), "f"(lo));
    return r;
}

// ===========================================================================
// fp32 -> fp16 conversion pass (16 elems/thread, MLP=4)
// ===========================================================================
__global__ void cvt_half_kernel(const float* __restrict__ in,
                                __half* __restrict__ out, int n16)
{
    int i = blockIdx.x * blockDim.x + threadIdx.x;
    if (i >= n16) return;
    float4 a = ((const float4*)in)[4 * i];
    float4 b = ((const float4*)in)[4 * i + 1];
    float4 c = ((const float4*)in)[4 * i + 2];
    float4 d = ((const float4*)in)[4 * i + 3];
    uint4 o0, o1;
    o0.x = pack_h2(a.x, a.y); o0.y = pack_h2(a.z, a.w);
    o0.z = pack_h2(b.x, b.y); o0.w = pack_h2(b.z, b.w);
    o1.x = pack_h2(c.x, c.y); o1.y = pack_h2(c.z, c.w);
    o1.z = pack_h2(d.x, d.y); o1.w = pack_h2(d.z, d.w);
    ((uint4*)out)[2 * i]     = o0;
    ((uint4*)out)[2 * i + 1] = o1;
}

// ===========================================================================
// fp16 mma.sync GEMM core + two epilogues (EPI=1: fused QKV epilogue).
// Q is pre-scaled by scale*log2(e) so flash can use exp2 directly.
// ===========================================================================
#define ASTRH 40
#define BSTRH 136
#define A_ST_B (128 * ASTRH * 2)
#define B_ST_B (32 * BSTRH * 2)
#define STAGE_B (A_ST_B + B_ST_B)
#define GSMEM_BYTES (3 * STAGE_B)

template <int EPI>
__global__ __launch_bounds__(256)
void gemm_f16(const __half* __restrict__ A, const __half* __restrict__ B,
              const float* __restrict__ bias, float* __restrict__ C,
              const float* __restrict__ cosb, const float* __restrict__ sinb,
              int K, int ldb, int N)
{
    extern __shared__ char smem[];
    const uint32_t sbase = smem_u32(smem);

    const int tid  = threadIdx.x;
    const int warp = tid >> 5;
    const int lane = tid & 31;
    const int g    = lane >> 2;
    const int t    = lane & 3;
    const int wm   = warp & 1;
    const int wn   = warp >> 1;
    const int brow = blockIdx.y * 128;
    const int n0   = blockIdx.x * 128;

    const int a_row = lane & 15;
    const int a_col = (lane >> 4) << 3;
    const int b_krow = (lane & 7) + (((lane >> 3) & 1) << 3);
    const int b_ncol = (lane >> 4) << 3;

    auto load_stage = [&](int s, int k0) {
        const __half* Ap = A + (size_t)brow * K + k0;
        const __half* Bp = B + (size_t)k0 * ldb + n0;
        const uint32_t sA = sbase + (uint32_t)s * STAGE_B;
        const uint32_t sB = sA + A_ST_B;
        #pragma unroll
        for (int p = 0; p < 2; p++) {
            int id = tid + p * 256;
            int r = id >> 2, c = (id & 3) << 3;
            cp_async16(sA + (uint32_t)(r * ASTRH + c) * 2, Ap + (size_t)r * K + c);
        }
        #pragma unroll
        for (int p = 0; p < 2; p++) {
            int id = tid + p * 256;
            int r = id >> 4, c = (id & 15) << 3;
            cp_async16(sB + (uint32_t)(r * BSTRH + c) * 2, Bp + (size_t)r * ldb + c);
        }
    };

    const int iters = K / 32;
    load_stage(0, 0);  CP_COMMIT();
    load_stage(1, 32); CP_COMMIT();

    float acc[4][4][4];
    #pragma unroll
    for (int mt = 0; mt < 4; mt++)
        #pragma unroll
        for (int nt = 0; nt < 4; nt++)
            #pragma unroll
            for (int q = 0; q < 4; q++) acc[mt][nt][q] = 0.0f;

    for (int i = 0; i < iters; i++) {
        CP_WAIT1();
        __syncthreads();
        if (i + 2 < iters) load_stage((i + 2) % 3, (i + 2) * 32);
        CP_COMMIT();

        const uint32_t sA = sbase + (uint32_t)(i % 3) * STAGE_B;
        const uint32_t sB = sA + A_ST_B;

        #pragma unroll
        for (int kk = 0; kk < 2; kk++) {
            uint32_t a[4][4];
            #pragma unroll
            for (int mt = 0; mt < 4; mt++) {
                uint32_t addr = sA + (uint32_t)((wm * 64 + mt * 16 + a_row) * ASTRH
                                                + kk * 16 + a_col) * 2;
                ldsm_x4(a[mt][0], a[mt][1], a[mt][2], a[mt][3], addr);
            }
            uint32_t b[4][2];
            #pragma unroll
            for (int np = 0; np < 2; np++) {
                uint32_t r0, r1, r2, r3;
                uint32_t addr = sB + (uint32_t)((kk * 16 + b_krow) * BSTRH
                                                + wn * 32 + np * 16 + b_ncol) * 2;
                ldsm_x4_t(r0, r1, r2, r3, addr);
                b[np * 2][0] = r0; b[np * 2][1] = r1;
                b[np * 2 + 1][0] = r2; b[np * 2 + 1][1] = r3;
            }
            #pragma unroll
            for (int mt = 0; mt < 4; mt++)
                #pragma unroll
                for (int nt = 0; nt < 4; nt++)
                    mma_f16(acc[mt][nt], a[mt], b[nt]);
        }
    }

    if (EPI == 0) {
        #pragma unroll
        for (int mt = 0; mt < 4; mt++) {
            #pragma unroll
            for (int nt = 0; nt < 4; nt++) {
                const int row = brow + wm * 64 + mt * 16 + g;
                const int col = n0 + wn * 32 + nt * 8 + 2 * t;
                float bx = 0.f, by = 0.f;
                if (bias) { bx = bias[col]; by = bias[col + 1]; }
                float2 v0 = make_float2(acc[mt][nt][0] + bx, acc[mt][nt][1] + by);
                float2 v1 = make_float2(acc[mt][nt][2] + bx, acc[mt][nt][3] + by);
                *(float2*)&C[(size_t)row * N + col]       = v0;
                *(float2*)&C[(size_t)(row + 8) * N + col] = v1;
            }
        }
    } else {
        // bias + RoPE + (scale*log2e for Q) + fp16 pack + dim-major V scatter
        const float scale = 0.08838834764831845f * 1.44269504088896f;
        #pragma unroll
        for (int nt = 0; nt < 4; nt++) {
            const int col  = n0 + wn * 32 + nt * 8 + 2 * t;
            const int head = col >> 7;
            const int dim  = col & 127;
            const bool do_rope = (dim < 64);
            const bool is_q    = (head < NUM_HEADS);
            const bool is_v    = (head >= NUM_HEADS + NUM_KV_HEADS);
            const float bx = bias[col];
            const float by = bias[col + 1];
            #pragma unroll
            for (int mt = 0; mt < 4; mt++) {
                const int row0 = brow + wm * 64 + mt * 16 + g;
                #pragma unroll
                for (int rr = 0; rr < 2; rr++) {
                    const int row = row0 + rr * 8;
                    float x = acc[mt][nt][2 * rr]     + bx;
                    float y = acc[mt][nt][2 * rr + 1] + by;
                    if (!is_v && do_rope) {
                        float cs = cosb[row * 64 + (dim >> 1)];
                        float sn = sinb[row * 64 + (dim >> 1)];
                        float x0 = x, x1 = y;
                        x = x0 * cs - x1 * sn;
                        y = x1 * cs + x0 * sn;
                    }
                    if (is_q) { x *= scale; y *= scale; }
                    *(uint32_t*)(g_qkvh + (size_t)row * QKV_OUT + col) = pack_h2(x, y);
                    if (is_v) {
                        int kvh = head - (NUM_HEADS + NUM_KV_HEADS);
                        g_vth[((size_t)(kvh * HEAD_DIM + dim))     * SEQLEN + row] = __float2half_rn(x);
                        g_vth[((size_t)(kvh * HEAD_DIM + dim + 1)) * SEQLEN + row] = __float2half_rn(y);
                    }
                }
            }
        }
    }
}

// ===========================================================================
// Flash attention (causal, GQA rep=16), fp16 mma + ldmatrix, exp2 softmax.
// grid.x = 16 flash q-blocks + FCVT_X converter columns: converter CTAs do a
// grid-stride w_o fp32->fp16 conversion overlapped under flash's compute.
// ===========================================================================
#define FBM 128
#define FBN 64
#define KSTRH 136
#define VSTRH 72
#define K_ST_B (FBN * KSTRH * 2)
#define V_ST_B (HEAD_DIM * VSTRH * 2)
#define FSTG_B (K_ST_B + V_ST_B)
#define FSMEM_BYTES (3 * FSTG_B)
#define FQB (SEQLEN / FBM)        // 16
#define FCVT_X 4                  // 4 x 32 = 128 converter CTAs

__global__ __launch_bounds__(256, 1) void flash_f16(
    __half* __restrict__ out,
    const float* __restrict__ wo_src, __half* __restrict__ wo_dst)
{
    // ---- converter CTAs: w_o fp32 -> fp16, then exit ----
    if (blockIdx.x >= FQB) {
        const int cid = (blockIdx.x - FQB) + FCVT_X * blockIdx.y;   // 0..127
        const int n16 = NQ * HIDDEN / 16;                            // 1M
        const int nthr = FCVT_X * NUM_HEADS * 256;                   // 32768
        for (int i = cid * 256 + threadIdx.x; i < n16; i += nthr) {
            float4 a = ((const float4*)wo_src)[4 * i];
            float4 b = ((const float4*)wo_src)[4 * i + 1];
            float4 c = ((const float4*)wo_src)[4 * i + 2];
            float4 d = ((const float4*)wo_src)[4 * i + 3];
            uint4 o0, o1;
            o0.x = pack_h2(a.x, a.y); o0.y = pack_h2(a.z, a.w);
            o0.z = pack_h2(b.x, b.y); o0.w = pack_h2(b.z, b.w);
            o1.x = pack_h2(c.x, c.y); o1.y = pack_h2(c.z, c.w);
            o1.z = pack_h2(d.x, d.y); o1.w = pack_h2(d.z, d.w);
            ((uint4*)wo_dst)[2 * i]     = o0;
            ((uint4*)wo_dst)[2 * i + 1] = o1;
        }
        return;
    }

    extern __shared__ char fsm[];
    const uint32_t sbase = smem_u32(fsm);

    const int tid  = threadIdx.x;
    const int warp = tid >> 5;
    const int lane = tid & 31;
    const int g    = lane >> 2;
    const int t    = lane & 3;
    const int h    = blockIdx.y;
    const int kvh  = h / REP;
    const int qi   = FQB - 1 - blockIdx.x;     // big blocks first
    const int q0   = qi * FBM;
    const int r0   = q0 + warp * 16 + g;
    const int r1   = r0 + 8;

    const int kq_key = (lane & 7) + ((lane >> 4) << 3);
    const int kq_dim = ((lane >> 3) & 1) << 3;
    const int pv_dim = (lane & 7) + ((lane >> 4) << 3);
    const int pv_key = ((lane >> 3) & 1) << 3;

    uint32_t qa[8][4];
    {
        const __half* qb = g_qkvh + (size_t)(q0 + warp * 16) * QKV_OUT + h * HEAD_DIM;
        #pragma unroll
        for (int ks = 0; ks < 8; ks++) {
            qa[ks][0] = *(const uint32_t*)(qb + (size_t)g       * QKV_OUT + ks * 16 + 2 * t);
            qa[ks][1] = *(const uint32_t*)(qb + (size_t)(g + 8) * QKV_OUT + ks * 16 + 2 * t);
            qa[ks][2] = *(const uint32_t*)(qb + (size_t)g       * QKV_OUT + ks * 16 + 8 + 2 * t);
            qa[ks][3] = *(const uint32_t*)(qb + (size_t)(g + 8) * QKV_OUT + ks * 16 + 8 + 2 * t);
        }
    }

    auto load_kv = [&](int s, int kb) {
        const uint32_t sK = sbase + (uint32_t)s * FSTG_B;
        const uint32_t sV = sK + K_ST_B;
        const __half* ksrc = g_qkvh + (size_t)(kb * FBN) * QKV_OUT + NQ + kvh * HEAD_DIM;
        const __half* vsrc = g_vth + (size_t)(kvh * HEAD_DIM) * SEQLEN + kb * FBN;
        #pragma unroll
        for (int p = 0; p < 4; p++) {
            int id = tid + p * 256;
            int r = id >> 4, c = (id & 15) << 3;
            cp_async16(sK + (uint32_t)(r * KSTRH + c) * 2, ksrc + (size_t)r * QKV_OUT + c);
        }
        #pragma unroll
        for (int p = 0; p < 4; p++) {
            int id = tid + p * 256;
            int r = id >> 3, c = (id & 7) << 3;
            cp_async16(sV + (uint32_t)(r * VSTRH + c) * 2, vsrc + (size_t)r * SEQLEN + c);
        }
    };

    float o[16][4];
    #pragma unroll
    for (int d = 0; d < 16; d++)
        #pragma unroll
        for (int q = 0; q < 4; q++) o[d][q] = 0.0f;
    float m0 = -1e30f, m1 = -1e30f, l0 = 0.0f, l1 = 0.0f;

    const int nkb = (q0 + FBM) / FBN;
    load_kv(0, 0); CP_COMMIT();
    load_kv(1, 1); CP_COMMIT();

    for (int kb = 0; kb < nkb; kb++) {
        CP_WAIT1();
        __syncthreads();
        if (kb + 2 < nkb) load_kv((kb + 2) % 3, kb + 2);
        CP_COMMIT();

        const uint32_t sKu = sbase + (uint32_t)(kb % 3) * FSTG_B;
        const uint32_t sVu = sKu + K_ST_B;

        float sc[8][4];
        #pragma unroll
        for (int j = 0; j < 8; j++)
            #pragma unroll
            for (int q = 0; q < 4; q++) sc[j][q] = 0.0f;

        #pragma unroll
        for (int ks = 0; ks < 8; ks++) {
            #pragma unroll
            for (int jp = 0; jp < 4; jp++) {
                uint32_t b0, b1, b2, b3;
                uint32_t addr = sKu + (uint32_t)((jp * 16 + kq_key) * KSTRH
                                                 + ks * 16 + kq_dim) * 2;
                ldsm_x4(b0, b1, b2, b3, addr);
                uint32_t bb0[2] = { b0, b1 };
                uint32_t bb1[2] = { b2, b3 };
                mma_f16(sc[2 * jp],     qa[ks], bb0);
                mma_f16(sc[2 * jp + 1], qa[ks], bb1);
            }
        }

        if (kb >= nkb - 2) {
            const int keyb = kb * FBN + 2 * t;
            #pragma unroll
            for (int j = 0; j < 8; j++) {
                int k0 = keyb + j * 8;
                if (k0     > r0) sc[j][0] = -1e30f;
                if (k0 + 1 > r0) sc[j][1] = -1e30f;
                if (k0     > r1) sc[j][2] = -1e30f;
                if (k0 + 1 > r1) sc[j][3] = -1e30f;
            }
        }

        float mx0 = -1e30f, mx1 = -1e30f;
        #pragma unroll
        for (int j = 0; j < 8; j++) {
            mx0 = fmaxf(mx0, fmaxf(sc[j][0], sc[j][1]));
            mx1 = fmaxf(mx1, fmaxf(sc[j][2], sc[j][3]));
        }
        mx0 = fmaxf(mx0, __shfl_xor_sync(0xffffffffu, mx0, 1));
        mx0 = fmaxf(mx0, __shfl_xor_sync(0xffffffffu, mx0, 2));
        mx1 = fmaxf(mx1, __shfl_xor_sync(0xffffffffu, mx1, 1));
        mx1 = fmaxf(mx1, __shfl_xor_sync(0xffffffffu, mx1, 2));
        const float mn0 = fmaxf(m0, mx0);
        const float mn1 = fmaxf(m1, mx1);
        const float c0 = exp2f(m0 - mn0);
        const float c1 = exp2f(m1 - mn1);
        m0 = mn0; m1 = mn1;
        l0 *= c0;  l1 *= c1;
        #pragma unroll
        for (int d = 0; d < 16; d++) {
            o[d][0] *= c0; o[d][1] *= c0;
            o[d][2] *= c1; o[d][3] *= c1;
        }

        uint32_t pa[4][4];
        #pragma unroll
        for (int jj = 0; jj < 4; jj++) {
            float p00 = exp2f(sc[2*jj][0]   - m0);
            float p01 = exp2f(sc[2*jj][1]   - m0);
            float p02 = exp2f(sc[2*jj][2]   - m1);
            float p03 = exp2f(sc[2*jj][3]   - m1);
            float p10 = exp2f(sc[2*jj+1][0] - m0);
            float p11 = exp2f(sc[2*jj+1][1] - m0);
            float p12 = exp2f(sc[2*jj+1][2] - m1);
            float p13 = exp2f(sc[2*jj+1][3] - m1);
            l0 += p00 + p01 + p10 + p11;
            l1 += p02 + p03 + p12 + p13;
            pa[jj][0] = pack_h2(p00, p01);
            pa[jj][1] = pack_h2(p02, p03);
            pa[jj][2] = pack_h2(p10, p11);
            pa[jj][3] = pack_h2(p12, p13);
        }

        #pragma unroll
        for (int jj = 0; jj < 4; jj++) {
            #pragma unroll
            for (int dp = 0; dp < 8; dp++) {
                uint32_t v0, v1, v2, v3;
                uint32_t addr = sVu + (uint32_t)((dp * 16 + pv_dim) * VSTRH
                                                 + jj * 16 + pv_key) * 2;
                ldsm_x4(v0, v1, v2, v3, addr);
                uint32_t bb0[2] = { v0, v1 };
                uint32_t bb1[2] = { v2, v3 };
                mma_f16(o[2 * dp],     pa[jj], bb0);
                mma_f16(o[2 * dp + 1], pa[jj], bb1);
            }
        }
    }

    l0 += __shfl_xor_sync(0xffffffffu, l0, 1);
    l0 += __shfl_xor_sync(0xffffffffu, l0, 2);
    l1 += __shfl_xor_sync(0xffffffffu, l1, 1);
    l1 += __shfl_xor_sync(0xffffffffu, l1, 2);
    const float inv0 = 1.0f / l0;
    const float inv1 = 1.0f / l1;

    __half* op0 = out + (size_t)r0 * NQ + h * HEAD_DIM + 2 * t;
    __half* op1 = out + (size_t)r1 * NQ + h * HEAD_DIM + 2 * t;
    #pragma unroll
    for (int d = 0; d < 16; d++) {
        *(uint32_t*)(op0 + d * 8) = pack_h2(o[d][0] * inv0, o[d][1] * inv0);
        *(uint32_t*)(op1 + d * 8) = pack_h2(o[d][2] * inv1, o[d][3] * inv1);
    }
}

// ---------------------------------------------------------------------------
// Launch
// ---------------------------------------------------------------------------
extern "C" void kernel_launch(void* const* d_in, const int* in_sizes, int n_in,
                              void* d_out, int out_size)
{
    const float* hidden = (const float*)d_in[0];
    const float* cosb   = (const float*)d_in[1];
    const float* sinb   = (const float*)d_in[2];
    const float* w_qkv  = (const float*)d_in[3];
    const float* b_qkv  = (const float*)d_in[4];
    const float* w_o    = (const float*)d_in[5];
    float* out = (float*)d_out;

    __half *Ah = nullptr, *Bh = nullptr, *Wo = nullptr, *attnh = nullptr;
    cudaGetSymbolAddress((void**)&Ah,    g_Ah);
    cudaGetSymbolAddress((void**)&Bh,    g_Bh);
    cudaGetSymbolAddress((void**)&Wo,    g_Wo);
    cudaGetSymbolAddress((void**)&attnh, g_attnh);

    cudaFuncSetAttribute(gemm_f16<0>, cudaFuncAttributeMaxDynamicSharedMemorySize, GSMEM_BYTES);
    cudaFuncSetAttribute(gemm_f16<1>, cudaFuncAttributeMaxDynamicSharedMemorySize, GSMEM_BYTES);
    cudaFuncSetAttribute(flash_f16,   cudaFuncAttributeMaxDynamicSharedMemorySize, FSMEM_BYTES);

    // 0) fp16 conversion of GEMM1 operands (MLP=4)
    {
        int n16 = SEQLEN * HIDDEN / 16;
        cvt_half_kernel<<<(n16 + 255) / 256, 256>>>(hidden, Ah, n16);
        n16 = HIDDEN * QKV_OUT / 16;
        cvt_half_kernel<<<(n16 + 255) / 256, 256>>>(w_qkv, Bh, n16);
    }

    // 1) QKV projection with fused bias+RoPE+scale(log2e)+fp16+V-transpose
    gemm_f16<1><<<dim3(QKV_OUT / 128, SEQLEN / 128), 256, GSMEM_BYTES>>>(
        Ah, Bh, b_qkv, nullptr, cosb, sinb, HIDDEN, QKV_OUT, QKV_OUT);

    // 2) flash attention + overlapped w_o conversion (extra converter CTAs)
    flash_f16<<<dim3(FQB + FCVT_X, NUM_HEADS), 256, FSMEM_BYTES>>>(attnh, w_o, Wo);

    // 3) output projection (fp16 mma, fp32 out)
    gemm_f16<0><<<dim3(HIDDEN / 128, SEQLEN / 128), 256, GSMEM_BYTES>>>(
        attnh, Wo, nullptr, out, nullptr, nullptr, NQ, HIDDEN, HIDDEN);
}

// round 16
// speedup vs baseline: 2.1138x; 1.0241x over previous
#include <cuda_runtime.h>
#include <cuda_fp16.h>
#include <cstdint>
#include <math.h>

#define SEQLEN   2048
#define HIDDEN   4096
#define NUM_HEADS 32
#define NUM_KV_HEADS 2
#define HEAD_DIM 128
#define QKV_OUT  ((NUM_HEADS + 2 * NUM_KV_HEADS) * HEAD_DIM)   // 4608
#define NQ       (NUM_HEADS * HEAD_DIM)                        // 4096
#define NKV      (NUM_KV_HEADS * HEAD_DIM)                     // 256
#define REP      (NUM_HEADS / NUM_KV_HEADS)                    // 16

// Scratch (device globals)
__device__ __half g_qkvh[SEQLEN * QKV_OUT];       // fp16 roped qkv (Q pre-scaled)
__device__ __half g_attnh[SEQLEN * NQ];           // fp16 attention out
__device__ __half g_Ah[SEQLEN * HIDDEN];          // fp16 hidden
__device__ __half g_Bh[HIDDEN * QKV_OUT];         // fp16 w_qkv
__device__ __half g_Wo[NQ * HIDDEN];              // fp16 w_o (converted inside flash launch)
__device__ __half g_vth[NUM_KV_HEADS * HEAD_DIM * SEQLEN];  // fp16 V dim-major

// ===========================================================================
// helpers
// ===========================================================================
__device__ __forceinline__ uint32_t smem_u32(const void* p) {
    uint32_t a;
    asm("{ .reg .u64 t; cvta.to.shared.u64 t, %1; cvt.u32.u64 %0, t; }"
        : "=r"(a) : "l"(p));
    return a;
}
__device__ __forceinline__ void cp_async16(uint32_t dst, const void* src) {
    asm volatile("cp.async.cg.shared.global [%0], [%1], 16;" :: "r"(dst), "l"(src));
}
#define CP_COMMIT() asm volatile("cp.async.commit_group;" ::: "memory")
#define CP_WAIT1()  asm volatile("cp.async.wait_group 1;" ::: "memory")

__device__ __forceinline__ void mma_f16(float* c, const uint32_t* a, const uint32_t* b) {
    asm volatile(
        "mma.sync.aligned.m16n8k16.row.col.f32.f16.f16.f32 "
        "{%0,%1,%2,%3}, {%4,%5,%6,%7}, {%8,%9}, {%0,%1,%2,%3};"
        : "+f"(c[0]), "+f"(c[1]), "+f"(c[2]), "+f"(c[3])
        : "r"(a[0]), "r"(a[1]), "r"(a[2]), "r"(a[3]), "r"(b[0]), "r"(b[1]));
}
__device__ __forceinline__ void ldsm_x4(uint32_t& r0, uint32_t& r1,
                                        uint32_t& r2, uint32_t& r3, uint32_t addr) {
    asm volatile("ldmatrix.sync.aligned.m8n8.x4.shared.b16 {%0,%1,%2,%3}, [%4];"
        : "=r"(r0), "=r"(r1), "=r"(r2), "=r"(r3) : "r"(addr));
}
__device__ __forceinline__ void ldsm_x4_t(uint32_t& r0, uint32_t& r1,
                                          uint32_t& r2, uint32_t& r3, uint32_t addr) {
    asm volatile("ldmatrix.sync.aligned.m8n8.x4.trans.shared.b16 {%0,%1,%2,%3}, [%4];"
        : "=r"(r0), "=r"(r1), "=r"(r2), "=r"(r3) : "r"(addr));
}
__device__ __forceinline__ uint32_t pack_h2(float lo, float hi) {
    uint32_t r;
    asm("cvt.rn.f16x2.f32 %0, %1, %2;" : "=r"(r) : "f"(hi), "f"(lo));
    return r;
}

// ===========================================================================
// fp32 -> fp16 conversion pass (16 elems/thread, MLP=4)
// ===========================================================================
__global__ void cvt_half_kernel(const float* __restrict__ in,
                                __half* __restrict__ out, int n16)
{
    int i = blockIdx.x * blockDim.x + threadIdx.x;
    if (i >= n16) return;
    float4 a = ((const float4*)in)[4 * i];
    float4 b = ((const float4*)in)[4 * i + 1];
    float4 c = ((const float4*)in)[4 * i + 2];
    float4 d = ((const float4*)in)[4 * i + 3];
    uint4 o0, o1;
    o0.x = pack_h2(a.x, a.y); o0.y = pack_h2(a.z, a.w);
    o0.z = pack_h2(b.x, b.y); o0.w = pack_h2(b.z, b.w);
    o1.x = pack_h2(c.x, c.y); o1.y = pack_h2(c.z, c.w);
    o1.z = pack_h2(d.x, d.y); o1.w = pack_h2(d.z, d.w);
    ((uint4*)out)[2 * i]     = o0;
    ((uint4*)out)[2 * i + 1] = o1;
}

// ===========================================================================
// fp16 mma.sync GEMM core + two epilogues (EPI=1: fused QKV epilogue).
// Q is pre-scaled by scale*log2(e) so flash can use exp2 directly.
// ===========================================================================
#define ASTRH 40
#define BSTRH 136
#define A_ST_B (128 * ASTRH * 2)
#define B_ST_B (32 * BSTRH * 2)
#define STAGE_B (A_ST_B + B_ST_B)
#define GSMEM_BYTES (3 * STAGE_B)

template <int EPI>
__global__ __launch_bounds__(256)
void gemm_f16(const __half* __restrict__ A, const __half* __restrict__ B,
              const float* __restrict__ bias, float* __restrict__ C,
              const float* __restrict__ cosb, const float* __restrict__ sinb,
              int K, int ldb, int N)
{
    extern __shared__ char smem[];
    const uint32_t sbase = smem_u32(smem);

    const int tid  = threadIdx.x;
    const int warp = tid >> 5;
    const int lane = tid & 31;
    const int g    = lane >> 2;
    const int t    = lane & 3;
    const int wm   = warp & 1;
    const int wn   = warp >> 1;
    const int brow = blockIdx.y * 128;
    const int n0   = blockIdx.x * 128;

    const int a_row = lane & 15;
    const int a_col = (lane >> 4) << 3;
    const int b_krow = (lane & 7) + (((lane >> 3) & 1) << 3);
    const int b_ncol = (lane >> 4) << 3;

    auto load_stage = [&](int s, int k0) {
        const __half* Ap = A + (size_t)brow * K + k0;
        const __half* Bp = B + (size_t)k0 * ldb + n0;
        const uint32_t sA = sbase + (uint32_t)s * STAGE_B;
        const uint32_t sB = sA + A_ST_B;
        #pragma unroll
        for (int p = 0; p < 2; p++) {
            int id = tid + p * 256;
            int r = id >> 2, c = (id & 3) << 3;
            cp_async16(sA + (uint32_t)(r * ASTRH + c) * 2, Ap + (size_t)r * K + c);
        }
        #pragma unroll
        for (int p = 0; p < 2; p++) {
            int id = tid + p * 256;
            int r = id >> 4, c = (id & 15) << 3;
            cp_async16(sB + (uint32_t)(r * BSTRH + c) * 2, Bp + (size_t)r * ldb + c);
        }
    };

    const int iters = K / 32;
    load_stage(0, 0);  CP_COMMIT();
    load_stage(1, 32); CP_COMMIT();

    float acc[4][4][4];
    #pragma unroll
    for (int mt = 0; mt < 4; mt++)
        #pragma unroll
        for (int nt = 0; nt < 4; nt++)
            #pragma unroll
            for (int q = 0; q < 4; q++) acc[mt][nt][q] = 0.0f;

    for (int i = 0; i < iters; i++) {
        CP_WAIT1();
        __syncthreads();
        if (i + 2 < iters) load_stage((i + 2) % 3, (i + 2) * 32);
        CP_COMMIT();

        const uint32_t sA = sbase + (uint32_t)(i % 3) * STAGE_B;
        const uint32_t sB = sA + A_ST_B;

        #pragma unroll
        for (int kk = 0; kk < 2; kk++) {
            uint32_t a[4][4];
            #pragma unroll
            for (int mt = 0; mt < 4; mt++) {
                uint32_t addr = sA + (uint32_t)((wm * 64 + mt * 16 + a_row) * ASTRH
                                                + kk * 16 + a_col) * 2;
                ldsm_x4(a[mt][0], a[mt][1], a[mt][2], a[mt][3], addr);
            }
            uint32_t b[4][2];
            #pragma unroll
            for (int np = 0; np < 2; np++) {
                uint32_t r0, r1, r2, r3;
                uint32_t addr = sB + (uint32_t)((kk * 16 + b_krow) * BSTRH
                                                + wn * 32 + np * 16 + b_ncol) * 2;
                ldsm_x4_t(r0, r1, r2, r3, addr);
                b[np * 2][0] = r0; b[np * 2][1] = r1;
                b[np * 2 + 1][0] = r2; b[np * 2 + 1][1] = r3;
            }
            #pragma unroll
            for (int mt = 0; mt < 4; mt++)
                #pragma unroll
                for (int nt = 0; nt < 4; nt++)
                    mma_f16(acc[mt][nt], a[mt], b[nt]);
        }
    }

    if (EPI == 0) {
        #pragma unroll
        for (int mt = 0; mt < 4; mt++) {
            #pragma unroll
            for (int nt = 0; nt < 4; nt++) {
                const int row = brow + wm * 64 + mt * 16 + g;
                const int col = n0 + wn * 32 + nt * 8 + 2 * t;
                float bx = 0.f, by = 0.f;
                if (bias) { bx = bias[col]; by = bias[col + 1]; }
                float2 v0 = make_float2(acc[mt][nt][0] + bx, acc[mt][nt][1] + by);
                float2 v1 = make_float2(acc[mt][nt][2] + bx, acc[mt][nt][3] + by);
                *(float2*)&C[(size_t)row * N + col]       = v0;
                *(float2*)&C[(size_t)(row + 8) * N + col] = v1;
            }
        }
    } else {
        // bias + RoPE + (scale*log2e for Q) + fp16 pack + dim-major V scatter
        const float scale = 0.08838834764831845f * 1.44269504088896f;
        #pragma unroll
        for (int nt = 0; nt < 4; nt++) {
            const int col  = n0 + wn * 32 + nt * 8 + 2 * t;
            const int head = col >> 7;
            const int dim  = col & 127;
            const bool do_rope = (dim < 64);
            const bool is_q    = (head < NUM_HEADS);
            const bool is_v    = (head >= NUM_HEADS + NUM_KV_HEADS);
            const float bx = bias[col];
            const float by = bias[col + 1];
            #pragma unroll
            for (int mt = 0; mt < 4; mt++) {
                const int row0 = brow + wm * 64 + mt * 16 + g;
                #pragma unroll
                for (int rr = 0; rr < 2; rr++) {
                    const int row = row0 + rr * 8;
                    float x = acc[mt][nt][2 * rr]     + bx;
                    float y = acc[mt][nt][2 * rr + 1] + by;
                    if (!is_v && do_rope) {
                        float cs = cosb[row * 64 + (dim >> 1)];
                        float sn = sinb[row * 64 + (dim >> 1)];
                        float x0 = x, x1 = y;
                        x = x0 * cs - x1 * sn;
                        y = x1 * cs + x0 * sn;
                    }
                    if (is_q) { x *= scale; y *= scale; }
                    *(uint32_t*)(g_qkvh + (size_t)row * QKV_OUT + col) = pack_h2(x, y);
                    if (is_v) {
                        int kvh = head - (NUM_HEADS + NUM_KV_HEADS);
                        g_vth[((size_t)(kvh * HEAD_DIM + dim))     * SEQLEN + row] = __float2half_rn(x);
                        g_vth[((size_t)(kvh * HEAD_DIM + dim + 1)) * SEQLEN + row] = __float2half_rn(y);
                    }
                }
            }
        }
    }
}

// ===========================================================================
// Flash attention (causal, GQA rep=16), fp16 mma + ldmatrix, exp2 softmax.
// BM=64 (4 warps / 128 threads), BN=64, 3-stage cp.async, 2 CTAs/SM so one
// CTA's softmax overlaps the other's mma. grid.x = 32 q-blocks + FCVT_X
// converter columns (w_o fp32->fp16 grid-stride, overlapped).
// ===========================================================================
#define FBM 64
#define FBN 64
#define KSTRH 136
#define VSTRH 72
#define K_ST_B (FBN * KSTRH * 2)          // 17408
#define V_ST_B (HEAD_DIM * VSTRH * 2)     // 18432
#define FSTG_B (K_ST_B + V_ST_B)          // 35840
#define FSMEM_BYTES (3 * FSTG_B)          // 107520 (x2 CTAs = 215040 < 228K)
#define FQB (SEQLEN / FBM)                // 32
#define FCVT_X 4                          // 4 x 32 = 128 converter CTAs

__global__ __launch_bounds__(128, 2) void flash_f16(
    __half* __restrict__ out,
    const float* __restrict__ wo_src, __half* __restrict__ wo_dst)
{
    // ---- converter CTAs: w_o fp32 -> fp16, then exit ----
    if (blockIdx.x >= FQB) {
        const int cid = (blockIdx.x - FQB) + FCVT_X * blockIdx.y;   // 0..127
        const int n16 = NQ * HIDDEN / 16;                            // 1M
        const int nthr = FCVT_X * NUM_HEADS * 128;                   // 16384
        for (int i = cid * 128 + threadIdx.x; i < n16; i += nthr) {
            float4 a = ((const float4*)wo_src)[4 * i];
            float4 b = ((const float4*)wo_src)[4 * i + 1];
            float4 c = ((const float4*)wo_src)[4 * i + 2];
            float4 d = ((const float4*)wo_src)[4 * i + 3];
            uint4 o0, o1;
            o0.x = pack_h2(a.x, a.y); o0.y = pack_h2(a.z, a.w);
            o0.z = pack_h2(b.x, b.y); o0.w = pack_h2(b.z, b.w);
            o1.x = pack_h2(c.x, c.y); o1.y = pack_h2(c.z, c.w);
            o1.z = pack_h2(d.x, d.y); o1.w = pack_h2(d.z, d.w);
            ((uint4*)wo_dst)[2 * i]     = o0;
            ((uint4*)wo_dst)[2 * i + 1] = o1;
        }
        return;
    }

    extern __shared__ char fsm[];
    const uint32_t sbase = smem_u32(fsm);

    const int tid  = threadIdx.x;
    const int warp = tid >> 5;
    const int lane = tid & 31;
    const int g    = lane >> 2;
    const int t    = lane & 3;
    const int h    = blockIdx.y;
    const int kvh  = h / REP;
    const int qi   = FQB - 1 - blockIdx.x;     // big blocks first
    const int q0   = qi * FBM;
    const int r0   = q0 + warp * 16 + g;
    const int r1   = r0 + 8;

    const int kq_key = (lane & 7) + ((lane >> 4) << 3);
    const int kq_dim = ((lane >> 3) & 1) << 3;
    const int pv_dim = (lane & 7) + ((lane >> 4) << 3);
    const int pv_key = ((lane >> 3) & 1) << 3;

    uint32_t qa[8][4];
    {
        const __half* qb = g_qkvh + (size_t)(q0 + warp * 16) * QKV_OUT + h * HEAD_DIM;
        #pragma unroll
        for (int ks = 0; ks < 8; ks++) {
            qa[ks][0] = *(const uint32_t*)(qb + (size_t)g       * QKV_OUT + ks * 16 + 2 * t);
            qa[ks][1] = *(const uint32_t*)(qb + (size_t)(g + 8) * QKV_OUT + ks * 16 + 2 * t);
            qa[ks][2] = *(const uint32_t*)(qb + (size_t)g       * QKV_OUT + ks * 16 + 8 + 2 * t);
            qa[ks][3] = *(const uint32_t*)(qb + (size_t)(g + 8) * QKV_OUT + ks * 16 + 8 + 2 * t);
        }
    }

    auto load_kv = [&](int s, int kb) {
        const uint32_t sK = sbase + (uint32_t)s * FSTG_B;
        const uint32_t sV = sK + K_ST_B;
        const __half* ksrc = g_qkvh + (size_t)(kb * FBN) * QKV_OUT + NQ + kvh * HEAD_DIM;
        const __half* vsrc = g_vth + (size_t)(kvh * HEAD_DIM) * SEQLEN + kb * FBN;
        #pragma unroll
        for (int p = 0; p < 8; p++) {
            int id = tid + p * 128;
            int r = id >> 4, c = (id & 15) << 3;    // K: 64 rows x 16 chunks
            cp_async16(sK + (uint32_t)(r * KSTRH + c) * 2, ksrc + (size_t)r * QKV_OUT + c);
        }
        #pragma unroll
        for (int p = 0; p < 8; p++) {
            int id = tid + p * 128;
            int r = id >> 3, c = (id & 7) << 3;     // V: 128 dims x 8 chunks
            cp_async16(sV + (uint32_t)(r * VSTRH + c) * 2, vsrc + (size_t)r * SEQLEN + c);
        }
    };

    float o[16][4];
    #pragma unroll
    for (int d = 0; d < 16; d++)
        #pragma unroll
        for (int q = 0; q < 4; q++) o[d][q] = 0.0f;
    float m0 = -1e30f, m1 = -1e30f, l0 = 0.0f, l1 = 0.0f;

    const int nkb = qi + 1;
    load_kv(0, 0); CP_COMMIT();
    load_kv(1, 1); CP_COMMIT();   // kb=1 may be unused (nkb==1): harmless valid read

    for (int kb = 0; kb < nkb; kb++) {
        CP_WAIT1();
        __syncthreads();
        if (kb + 2 < nkb) load_kv((kb + 2) % 3, kb + 2);
        CP_COMMIT();

        const uint32_t sKu = sbase + (uint32_t)(kb % 3) * FSTG_B;
        const uint32_t sVu = sKu + K_ST_B;

        float sc[8][4];
        #pragma unroll
        for (int j = 0; j < 8; j++)
            #pragma unroll
            for (int q = 0; q < 4; q++) sc[j][q] = 0.0f;

        #pragma unroll
        for (int ks = 0; ks < 8; ks++) {
            #pragma unroll
            for (int jp = 0; jp < 4; jp++) {
                uint32_t b0, b1, b2, b3;
                uint32_t addr = sKu + (uint32_t)((jp * 16 + kq_key) * KSTRH
                                                 + ks * 16 + kq_dim) * 2;
                ldsm_x4(b0, b1, b2, b3, addr);
                uint32_t bb0[2] = { b0, b1 };
                uint32_t bb1[2] = { b2, b3 };
                mma_f16(sc[2 * jp],     qa[ks], bb0);
                mma_f16(sc[2 * jp + 1], qa[ks], bb1);
            }
        }

        // causal mask: BM<=BN, so only the final (diagonal) block crosses
        if (kb == nkb - 1) {
            const int keyb = kb * FBN + 2 * t;
            #pragma unroll
            for (int j = 0; j < 8; j++) {
                int k0 = keyb + j * 8;
                if (k0     > r0) sc[j][0] = -1e30f;
                if (k0 + 1 > r0) sc[j][1] = -1e30f;
                if (k0     > r1) sc[j][2] = -1e30f;
                if (k0 + 1 > r1) sc[j][3] = -1e30f;
            }
        }

        float mx0 = -1e30f, mx1 = -1e30f;
        #pragma unroll
        for (int j = 0; j < 8; j++) {
            mx0 = fmaxf(mx0, fmaxf(sc[j][0], sc[j][1]));
            mx1 = fmaxf(mx1, fmaxf(sc[j][2], sc[j][3]));
        }
        mx0 = fmaxf(mx0, __shfl_xor_sync(0xffffffffu, mx0, 1));
        mx0 = fmaxf(mx0, __shfl_xor_sync(0xffffffffu, mx0, 2));
        mx1 = fmaxf(mx1, __shfl_xor_sync(0xffffffffu, mx1, 1));
        mx1 = fmaxf(mx1, __shfl_xor_sync(0xffffffffu, mx1, 2));
        const float mn0 = fmaxf(m0, mx0);
        const float mn1 = fmaxf(m1, mx1);
        const float c0 = exp2f(m0 - mn0);
        const float c1 = exp2f(m1 - mn1);
        m0 = mn0; m1 = mn1;
        l0 *= c0;  l1 *= c1;
        #pragma unroll
        for (int d = 0; d < 16; d++) {
            o[d][0] *= c0; o[d][1] *= c0;
            o[d][2] *= c1; o[d][3] *= c1;
        }

        uint32_t pa[4][4];
        #pragma unroll
        for (int jj = 0; jj < 4; jj++) {
            float p00 = exp2f(sc[2*jj][0]   - m0);
            float p01 = exp2f(sc[2*jj][1]   - m0);
            float p02 = exp2f(sc[2*jj][2]   - m1);
            float p03 = exp2f(sc[2*jj][3]   - m1);
            float p10 = exp2f(sc[2*jj+1][0] - m0);
            float p11 = exp2f(sc[2*jj+1][1] - m0);
            float p12 = exp2f(sc[2*jj+1][2] - m1);
            float p13 = exp2f(sc[2*jj+1][3] - m1);
            l0 += p00 + p01 + p10 + p11;
            l1 += p02 + p03 + p12 + p13;
            pa[jj][0] = pack_h2(p00, p01);
            pa[jj][1] = pack_h2(p02, p03);
            pa[jj][2] = pack_h2(p10, p11);
            pa[jj][3] = pack_h2(p12, p13);
        }

        #pragma unroll
        for (int jj = 0; jj < 4; jj++) {
            #pragma unroll
            for (int dp = 0; dp < 8; dp++) {
                uint32_t v0, v1, v2, v3;
                uint32_t addr = sVu + (uint32_t)((dp * 16 + pv_dim) * VSTRH
                                                 + jj * 16 + pv_key) * 2;
                ldsm_x4(v0, v1, v2, v3, addr);
                uint32_t bb0[2] = { v0, v1 };
                uint32_t bb1[2] = { v2, v3 };
                mma_f16(o[2 * dp],     pa[jj], bb0);
                mma_f16(o[2 * dp + 1], pa[jj], bb1);
            }
        }
    }

    l0 += __shfl_xor_sync(0xffffffffu, l0, 1);
    l0 += __shfl_xor_sync(0xffffffffu, l0, 2);
    l1 += __shfl_xor_sync(0xffffffffu, l1, 1);
    l1 += __shfl_xor_sync(0xffffffffu, l1, 2);
    const float inv0 = 1.0f / l0;
    const float inv1 = 1.0f / l1;

    __half* op0 = out + (size_t)r0 * NQ + h * HEAD_DIM + 2 * t;
    __half* op1 = out + (size_t)r1 * NQ + h * HEAD_DIM + 2 * t;
    #pragma unroll
    for (int d = 0; d < 16; d++) {
        *(uint32_t*)(op0 + d * 8) = pack_h2(o[d][0] * inv0, o[d][1] * inv0);
        *(uint32_t*)(op1 + d * 8) = pack_h2(o[d][2] * inv1, o[d][3] * inv1);
    }
}

// ---------------------------------------------------------------------------
// Launch
// ---------------------------------------------------------------------------
extern "C" void kernel_launch(void* const* d_in, const int* in_sizes, int n_in,
                              void* d_out, int out_size)
{
    const float* hidden = (const float*)d_in[0];
    const float* cosb   = (const float*)d_in[1];
    const float* sinb   = (const float*)d_in[2];
    const float* w_qkv  = (const float*)d_in[3];
    const float* b_qkv  = (const float*)d_in[4];
    const float* w_o    = (const float*)d_in[5];
    float* out = (float*)d_out;

    __half *Ah = nullptr, *Bh = nullptr, *Wo = nullptr, *attnh = nullptr;
    cudaGetSymbolAddress((void**)&Ah,    g_Ah);
    cudaGetSymbolAddress((void**)&Bh,    g_Bh);
    cudaGetSymbolAddress((void**)&Wo,    g_Wo);
    cudaGetSymbolAddress((void**)&attnh, g_attnh);

    cudaFuncSetAttribute(gemm_f16<0>, cudaFuncAttributeMaxDynamicSharedMemorySize, GSMEM_BYTES);
    cudaFuncSetAttribute(gemm_f16<1>, cudaFuncAttributeMaxDynamicSharedMemorySize, GSMEM_BYTES);
    cudaFuncSetAttribute(flash_f16,   cudaFuncAttributeMaxDynamicSharedMemorySize, FSMEM_BYTES);

    // 0) fp16 conversion of GEMM1 operands (MLP=4)
    {
        int n16 = SEQLEN * HIDDEN / 16;
        cvt_half_kernel<<<(n16 + 255) / 256, 256>>>(hidden, Ah, n16);
        n16 = HIDDEN * QKV_OUT / 16;
        cvt_half_kernel<<<(n16 + 255) / 256, 256>>>(w_qkv, Bh, n16);
    }

    // 1) QKV projection with fused bias+RoPE+scale(log2e)+fp16+V-transpose
    gemm_f16<1><<<dim3(QKV_OUT / 128, SEQLEN / 128), 256, GSMEM_BYTES>>>(
        Ah, Bh, b_qkv, nullptr, cosb, sinb, HIDDEN, QKV_OUT, QKV_OUT);

    // 2) flash attention (2 CTAs/SM) + overlapped w_o conversion
    flash_f16<<<dim3(FQB + FCVT_X, NUM_HEADS), 128, FSMEM_BYTES>>>(attnh, w_o, Wo);

    // 3) output projection (fp16 mma, fp32 out)
    gemm_f16<0><<<dim3(HIDDEN / 128, SEQLEN / 128), 256, GSMEM_BYTES>>>(
        attnh, Wo, nullptr, out, nullptr, nullptr, NQ, HIDDEN, HIDDEN);
}

// round 17
// speedup vs baseline: 2.3226x; 1.0988x over previous
#include <cuda_runtime.h>
#include <cuda_fp16.h>
#include <cstdint>
#include <math.h>

#define SEQLEN   2048
#define HIDDEN   4096
#define NUM_HEADS 32
#define NUM_KV_HEADS 2
#define HEAD_DIM 128
#define QKV_OUT  ((NUM_HEADS + 2 * NUM_KV_HEADS) * HEAD_DIM)   // 4608
#define NQ       (NUM_HEADS * HEAD_DIM)                        // 4096
#define NKV      (NUM_KV_HEADS * HEAD_DIM)                     // 256
#define REP      (NUM_HEADS / NUM_KV_HEADS)                    // 16

// Scratch (device globals)
__device__ __half g_qkvh[SEQLEN * QKV_OUT];       // fp16 roped qkv (Q pre-scaled)
__device__ __half g_attnh[SEQLEN * NQ];           // fp16 attention out
__device__ __half g_Ah[SEQLEN * HIDDEN];          // fp16 hidden
__device__ __half g_Bh[HIDDEN * QKV_OUT];         // fp16 w_qkv
__device__ __half g_Wo[NQ * HIDDEN];              // fp16 w_o (converted inside flash launch)
__device__ __half g_vth[NUM_KV_HEADS * HEAD_DIM * SEQLEN];  // fp16 V dim-major

// ===========================================================================
// helpers
// ===========================================================================
__device__ __forceinline__ uint32_t smem_u32(const void* p) {
    uint32_t a;
    asm("{ .reg .u64 t; cvta.to.shared.u64 t, %1; cvt.u32.u64 %0, t; }"
        : "=r"(a) : "l"(p));
    return a;
}
__device__ __forceinline__ void cp_async16(uint32_t dst, const void* src) {
    asm volatile("cp.async.cg.shared.global [%0], [%1], 16;" :: "r"(dst), "l"(src));
}
#define CP_COMMIT() asm volatile("cp.async.commit_group;" ::: "memory")
#define CP_WAIT1()  asm volatile("cp.async.wait_group 1;" ::: "memory")

__device__ __forceinline__ void mma_f16(float* c, const uint32_t* a, const uint32_t* b) {
    asm volatile(
        "mma.sync.aligned.m16n8k16.row.col.f32.f16.f16.f32 "
        "{%0,%1,%2,%3}, {%4,%5,%6,%7}, {%8,%9}, {%0,%1,%2,%3};"
        : "+f"(c[0]), "+f"(c[1]), "+f"(c[2]), "+f"(c[3])
        : "r"(a[0]), "r"(a[1]), "r"(a[2]), "r"(a[3]), "r"(b[0]), "r"(b[1]));
}
__device__ __forceinline__ void ldsm_x4(uint32_t& r0, uint32_t& r1,
                                        uint32_t& r2, uint32_t& r3, uint32_t addr) {
    asm volatile("ldmatrix.sync.aligned.m8n8.x4.shared.b16 {%0,%1,%2,%3}, [%4];"
        : "=r"(r0), "=r"(r1), "=r"(r2), "=r"(r3) : "r"(addr));
}
__device__ __forceinline__ void ldsm_x4_t(uint32_t& r0, uint32_t& r1,
                                          uint32_t& r2, uint32_t& r3, uint32_t addr) {
    asm volatile("ldmatrix.sync.aligned.m8n8.x4.trans.shared.b16 {%0,%1,%2,%3}, [%4];"
        : "=r"(r0), "=r"(r1), "=r"(r2), "=r"(r3) : "r"(addr));
}
__device__ __forceinline__ uint32_t pack_h2(float lo, float hi) {
    uint32_t r;
    asm("cvt.rn.f16x2.f32 %0, %1, %2;" : "=r"(r) : "f"(hi), "f"(lo));
    return r;
}

// ===========================================================================
// fused fp32 -> fp16 conversion of hidden AND w_qkv in one launch
// (16 elems/thread, MLP=4)
// ===========================================================================
#define N16_A (SEQLEN * HIDDEN / 16)
#define N16_B (HIDDEN * QKV_OUT / 16)

__global__ void cvt_both_kernel(const float* __restrict__ inA, __half* __restrict__ outA,
                                const float* __restrict__ inB, __half* __restrict__ outB)
{
    int i = blockIdx.x * blockDim.x + threadIdx.x;
    const float* in;
    __half* out;
    if (i < N16_A) { in = inA; out = outA; }
    else if (i < N16_A + N16_B) { in = inB; out = outB; i -= N16_A; }
    else return;
    float4 a = ((const float4*)in)[4 * i];
    float4 b = ((const float4*)in)[4 * i + 1];
    float4 c = ((const float4*)in)[4 * i + 2];
    float4 d = ((const float4*)in)[4 * i + 3];
    uint4 o0, o1;
    o0.x = pack_h2(a.x, a.y); o0.y = pack_h2(a.z, a.w);
    o0.z = pack_h2(b.x, b.y); o0.w = pack_h2(b.z, b.w);
    o1.x = pack_h2(c.x, c.y); o1.y = pack_h2(c.z, c.w);
    o1.z = pack_h2(d.x, d.y); o1.w = pack_h2(d.z, d.w);
    ((uint4*)out)[2 * i]     = o0;
    ((uint4*)out)[2 * i + 1] = o1;
}

// ===========================================================================
// fp16 mma.sync GEMM core + two epilogues (EPI=1: fused QKV epilogue).
// __launch_bounds__(256, 2): cap regs at 128 so 2 CTAs/SM co-schedule —
// one CTA's barrier/ldsm head overlaps the other's HMMA stream.
// ===========================================================================
#define ASTRH 40
#define BSTRH 136
#define A_ST_B (128 * ASTRH * 2)
#define B_ST_B (32 * BSTRH * 2)
#define STAGE_B (A_ST_B + B_ST_B)
#define GSMEM_BYTES (3 * STAGE_B)          // 56832 (x2 CTAs = 113664)

template <int EPI>
__global__ __launch_bounds__(256, 2)
void gemm_f16(const __half* __restrict__ A, const __half* __restrict__ B,
              const float* __restrict__ bias, float* __restrict__ C,
              const float* __restrict__ cosb, const float* __restrict__ sinb,
              int K, int ldb, int N)
{
    extern __shared__ char smem[];
    const uint32_t sbase = smem_u32(smem);

    const int tid  = threadIdx.x;
    const int warp = tid >> 5;
    const int lane = tid & 31;
    const int g    = lane >> 2;
    const int t    = lane & 3;
    const int wm   = warp & 1;
    const int wn   = warp >> 1;
    const int brow = blockIdx.y * 128;
    const int n0   = blockIdx.x * 128;

    const int a_row = lane & 15;
    const int a_col = (lane >> 4) << 3;
    const int b_krow = (lane & 7) + (((lane >> 3) & 1) << 3);
    const int b_ncol = (lane >> 4) << 3;

    auto load_stage = [&](int s, int k0) {
        const __half* Ap = A + (size_t)brow * K + k0;
        const __half* Bp = B + (size_t)k0 * ldb + n0;
        const uint32_t sA = sbase + (uint32_t)s * STAGE_B;
        const uint32_t sB = sA + A_ST_B;
        #pragma unroll
        for (int p = 0; p < 2; p++) {
            int id = tid + p * 256;
            int r = id >> 2, c = (id & 3) << 3;
            cp_async16(sA + (uint32_t)(r * ASTRH + c) * 2, Ap + (size_t)r * K + c);
        }
        #pragma unroll
        for (int p = 0; p < 2; p++) {
            int id = tid + p * 256;
            int r = id >> 4, c = (id & 15) << 3;
            cp_async16(sB + (uint32_t)(r * BSTRH + c) * 2, Bp + (size_t)r * ldb + c);
        }
    };

    const int iters = K / 32;
    load_stage(0, 0);  CP_COMMIT();
    load_stage(1, 32); CP_COMMIT();

    float acc[4][4][4];
    #pragma unroll
    for (int mt = 0; mt < 4; mt++)
        #pragma unroll
        for (int nt = 0; nt < 4; nt++)
            #pragma unroll
            for (int q = 0; q < 4; q++) acc[mt][nt][q] = 0.0f;

    for (int i = 0; i < iters; i++) {
        CP_WAIT1();
        __syncthreads();
        if (i + 2 < iters) load_stage((i + 2) % 3, (i + 2) * 32);
        CP_COMMIT();

        const uint32_t sA = sbase + (uint32_t)(i % 3) * STAGE_B;
        const uint32_t sB = sA + A_ST_B;

        #pragma unroll
        for (int kk = 0; kk < 2; kk++) {
            uint32_t a[4][4];
            #pragma unroll
            for (int mt = 0; mt < 4; mt++) {
                uint32_t addr = sA + (uint32_t)((wm * 64 + mt * 16 + a_row) * ASTRH
                                                + kk * 16 + a_col) * 2;
                ldsm_x4(a[mt][0], a[mt][1], a[mt][2], a[mt][3], addr);
            }
            uint32_t b[4][2];
            #pragma unroll
            for (int np = 0; np < 2; np++) {
                uint32_t r0, r1, r2, r3;
                uint32_t addr = sB + (uint32_t)((kk * 16 + b_krow) * BSTRH
                                                + wn * 32 + np * 16 + b_ncol) * 2;
                ldsm_x4_t(r0, r1, r2, r3, addr);
                b[np * 2][0] = r0; b[np * 2][1] = r1;
                b[np * 2 + 1][0] = r2; b[np * 2 + 1][1] = r3;
            }
            #pragma unroll
            for (int mt = 0; mt < 4; mt++)
                #pragma unroll
                for (int nt = 0; nt < 4; nt++)
                    mma_f16(acc[mt][nt], a[mt], b[nt]);
        }
    }

    if (EPI == 0) {
        #pragma unroll
        for (int mt = 0; mt < 4; mt++) {
            #pragma unroll
            for (int nt = 0; nt < 4; nt++) {
                const int row = brow + wm * 64 + mt * 16 + g;
                const int col = n0 + wn * 32 + nt * 8 + 2 * t;
                float bx = 0.f, by = 0.f;
                if (bias) { bx = bias[col]; by = bias[col + 1]; }
                float2 v0 = make_float2(acc[mt][nt][0] + bx, acc[mt][nt][1] + by);
                float2 v1 = make_float2(acc[mt][nt][2] + bx, acc[mt][nt][3] + by);
                *(float2*)&C[(size_t)row * N + col]       = v0;
                *(float2*)&C[(size_t)(row + 8) * N + col] = v1;
            }
        }
    } else {
        // bias + RoPE + (scale*log2e for Q) + fp16 pack + dim-major V scatter
        const float scale = 0.08838834764831845f * 1.44269504088896f;
        #pragma unroll
        for (int nt = 0; nt < 4; nt++) {
            const int col  = n0 + wn * 32 + nt * 8 + 2 * t;
            const int head = col >> 7;
            const int dim  = col & 127;
            const bool do_rope = (dim < 64);
            const bool is_q    = (head < NUM_HEADS);
            const bool is_v    = (head >= NUM_HEADS + NUM_KV_HEADS);
            const float bx = bias[col];
            const float by = bias[col + 1];
            #pragma unroll
            for (int mt = 0; mt < 4; mt++) {
                const int row0 = brow + wm * 64 + mt * 16 + g;
                #pragma unroll
                for (int rr = 0; rr < 2; rr++) {
                    const int row = row0 + rr * 8;
                    float x = acc[mt][nt][2 * rr]     + bx;
                    float y = acc[mt][nt][2 * rr + 1] + by;
                    if (!is_v && do_rope) {
                        float cs = cosb[row * 64 + (dim >> 1)];
                        float sn = sinb[row * 64 + (dim >> 1)];
                        float x0 = x, x1 = y;
                        x = x0 * cs - x1 * sn;
                        y = x1 * cs + x0 * sn;
                    }
                    if (is_q) { x *= scale; y *= scale; }
                    *(uint32_t*)(g_qkvh + (size_t)row * QKV_OUT + col) = pack_h2(x, y);
                    if (is_v) {
                        int kvh = head - (NUM_HEADS + NUM_KV_HEADS);
                        g_vth[((size_t)(kvh * HEAD_DIM + dim))     * SEQLEN + row] = __float2half_rn(x);
                        g_vth[((size_t)(kvh * HEAD_DIM + dim + 1)) * SEQLEN + row] = __float2half_rn(y);
                    }
                }
            }
        }
    }
}

// ===========================================================================
// Flash attention (causal, GQA rep=16), fp16 mma + ldmatrix, exp2 softmax.
// BM=64 (4 warps / 128 threads), BN=64, 3-stage cp.async, 2 CTAs/SM.
// grid.x = 32 q-blocks + FCVT_X converter columns (w_o cvt overlapped).
// (unchanged from R16 — measured ~78% of fp16 mma roofline)
// ===========================================================================
#define FBM 64
#define FBN 64
#define KSTRH 136
#define VSTRH 72
#define K_ST_B (FBN * KSTRH * 2)
#define V_ST_B (HEAD_DIM * VSTRH * 2)
#define FSTG_B (K_ST_B + V_ST_B)
#define FSMEM_BYTES (3 * FSTG_B)
#define FQB (SEQLEN / FBM)                // 32
#define FCVT_X 4

__global__ __launch_bounds__(128, 2) void flash_f16(
    __half* __restrict__ out,
    const float* __restrict__ wo_src, __half* __restrict__ wo_dst)
{
    if (blockIdx.x >= FQB) {
        const int cid = (blockIdx.x - FQB) + FCVT_X * blockIdx.y;
        const int n16 = NQ * HIDDEN / 16;
        const int nthr = FCVT_X * NUM_HEADS * 128;
        for (int i = cid * 128 + threadIdx.x; i < n16; i += nthr) {
            float4 a = ((const float4*)wo_src)[4 * i];
            float4 b = ((const float4*)wo_src)[4 * i + 1];
            float4 c = ((const float4*)wo_src)[4 * i + 2];
            float4 d = ((const float4*)wo_src)[4 * i + 3];
            uint4 o0, o1;
            o0.x = pack_h2(a.x, a.y); o0.y = pack_h2(a.z, a.w);
            o0.z = pack_h2(b.x, b.y); o0.w = pack_h2(b.z, b.w);
            o1.x = pack_h2(c.x, c.y); o1.y = pack_h2(c.z, c.w);
            o1.z = pack_h2(d.x, d.y); o1.w = pack_h2(d.z, d.w);
            ((uint4*)wo_dst)[2 * i]     = o0;
            ((uint4*)wo_dst)[2 * i + 1] = o1;
        }
        return;
    }

    extern __shared__ char fsm[];
    const uint32_t sbase = smem_u32(fsm);

    const int tid  = threadIdx.x;
    const int warp = tid >> 5;
    const int lane = tid & 31;
    const int g    = lane >> 2;
    const int t    = lane & 3;
    const int h    = blockIdx.y;
    const int kvh  = h / REP;
    const int qi   = FQB - 1 - blockIdx.x;
    const int q0   = qi * FBM;
    const int r0   = q0 + warp * 16 + g;
    const int r1   = r0 + 8;

    const int kq_key = (lane & 7) + ((lane >> 4) << 3);
    const int kq_dim = ((lane >> 3) & 1) << 3;
    const int pv_dim = (lane & 7) + ((lane >> 4) << 3);
    const int pv_key = ((lane >> 3) & 1) << 3;

    uint32_t qa[8][4];
    {
        const __half* qb = g_qkvh + (size_t)(q0 + warp * 16) * QKV_OUT + h * HEAD_DIM;
        #pragma unroll
        for (int ks = 0; ks < 8; ks++) {
            qa[ks][0] = *(const uint32_t*)(qb + (size_t)g       * QKV_OUT + ks * 16 + 2 * t);
            qa[ks][1] = *(const uint32_t*)(qb + (size_t)(g + 8) * QKV_OUT + ks * 16 + 2 * t);
            qa[ks][2] = *(const uint32_t*)(qb + (size_t)g       * QKV_OUT + ks * 16 + 8 + 2 * t);
            qa[ks][3] = *(const uint32_t*)(qb + (size_t)(g + 8) * QKV_OUT + ks * 16 + 8 + 2 * t);
        }
    }

    auto load_kv = [&](int s, int kb) {
        const uint32_t sK = sbase + (uint32_t)s * FSTG_B;
        const uint32_t sV = sK + K_ST_B;
        const __half* ksrc = g_qkvh + (size_t)(kb * FBN) * QKV_OUT + NQ + kvh * HEAD_DIM;
        const __half* vsrc = g_vth + (size_t)(kvh * HEAD_DIM) * SEQLEN + kb * FBN;
        #pragma unroll
        for (int p = 0; p < 8; p++) {
            int id = tid + p * 128;
            int r = id >> 4, c = (id & 15) << 3;
            cp_async16(sK + (uint32_t)(r * KSTRH + c) * 2, ksrc + (size_t)r * QKV_OUT + c);
        }
        #pragma unroll
        for (int p = 0; p < 8; p++) {
            int id = tid + p * 128;
            int r = id >> 3, c = (id & 7) << 3;
            cp_async16(sV + (uint32_t)(r * VSTRH + c) * 2, vsrc + (size_t)r * SEQLEN + c);
        }
    };

    float o[16][4];
    #pragma unroll
    for (int d = 0; d < 16; d++)
        #pragma unroll
        for (int q = 0; q < 4; q++) o[d][q] = 0.0f;
    float m0 = -1e30f, m1 = -1e30f, l0 = 0.0f, l1 = 0.0f;

    const int nkb = qi + 1;
    load_kv(0, 0); CP_COMMIT();
    load_kv(1, 1); CP_COMMIT();

    for (int kb = 0; kb < nkb; kb++) {
        CP_WAIT1();
        __syncthreads();
        if (kb + 2 < nkb) load_kv((kb + 2) % 3, kb + 2);
        CP_COMMIT();

        const uint32_t sKu = sbase + (uint32_t)(kb % 3) * FSTG_B;
        const uint32_t sVu = sKu + K_ST_B;

        float sc[8][4];
        #pragma unroll
        for (int j = 0; j < 8; j++)
            #pragma unroll
            for (int q = 0; q < 4; q++) sc[j][q] = 0.0f;

        #pragma unroll
        for (int ks = 0; ks < 8; ks++) {
            #pragma unroll
            for (int jp = 0; jp < 4; jp++) {
                uint32_t b0, b1, b2, b3;
                uint32_t addr = sKu + (uint32_t)((jp * 16 + kq_key) * KSTRH
                                                 + ks * 16 + kq_dim) * 2;
                ldsm_x4(b0, b1, b2, b3, addr);
                uint32_t bb0[2] = { b0, b1 };
                uint32_t bb1[2] = { b2, b3 };
                mma_f16(sc[2 * jp],     qa[ks], bb0);
                mma_f16(sc[2 * jp + 1], qa[ks], bb1);
            }
        }

        if (kb == nkb - 1) {
            const int keyb = kb * FBN + 2 * t;
            #pragma unroll
            for (int j = 0; j < 8; j++) {
                int k0 = keyb + j * 8;
                if (k0     > r0) sc[j][0] = -1e30f;
                if (k0 + 1 > r0) sc[j][1] = -1e30f;
                if (k0     > r1) sc[j][2] = -1e30f;
                if (k0 + 1 > r1) sc[j][3] = -1e30f;
            }
        }

        float mx0 = -1e30f, mx1 = -1e30f;
        #pragma unroll
        for (int j = 0; j < 8; j++) {
            mx0 = fmaxf(mx0, fmaxf(sc[j][0], sc[j][1]));
            mx1 = fmaxf(mx1, fmaxf(sc[j][2], sc[j][3]));
        }
        mx0 = fmaxf(mx0, __shfl_xor_sync(0xffffffffu, mx0, 1));
        mx0 = fmaxf(mx0, __shfl_xor_sync(0xffffffffu, mx0, 2));
        mx1 = fmaxf(mx1, __shfl_xor_sync(0xffffffffu, mx1, 1));
        mx1 = fmaxf(mx1, __shfl_xor_sync(0xffffffffu, mx1, 2));
        const float mn0 = fmaxf(m0, mx0);
        const float mn1 = fmaxf(m1, mx1);
        const float c0 = exp2f(m0 - mn0);
        const float c1 = exp2f(m1 - mn1);
        m0 = mn0; m1 = mn1;
        l0 *= c0;  l1 *= c1;
        #pragma unroll
        for (int d = 0; d < 16; d++) {
            o[d][0] *= c0; o[d][1] *= c0;
            o[d][2] *= c1; o[d][3] *= c1;
        }

        uint32_t pa[4][4];
        #pragma unroll
        for (int jj = 0; jj < 4; jj++) {
            float p00 = exp2f(sc[2*jj][0]   - m0);
            float p01 = exp2f(sc[2*jj][1]   - m0);
            float p02 = exp2f(sc[2*jj][2]   - m1);
            float p03 = exp2f(sc[2*jj][3]   - m1);
            float p10 = exp2f(sc[2*jj+1][0] - m0);
            float p11 = exp2f(sc[2*jj+1][1] - m0);
            float p12 = exp2f(sc[2*jj+1][2] - m1);
            float p13 = exp2f(sc[2*jj+1][3] - m1);
            l0 += p00 + p01 + p10 + p11;
            l1 += p02 + p03 + p12 + p13;
            pa[jj][0] = pack_h2(p00, p01);
            pa[jj][1] = pack_h2(p02, p03);
            pa[jj][2] = pack_h2(p10, p11);
            pa[jj][3] = pack_h2(p12, p13);
        }

        #pragma unroll
        for (int jj = 0; jj < 4; jj++) {
            #pragma unroll
            for (int dp = 0; dp < 8; dp++) {
                uint32_t v0, v1, v2, v3;
                uint32_t addr = sVu + (uint32_t)((dp * 16 + pv_dim) * VSTRH
                                                 + jj * 16 + pv_key) * 2;
                ldsm_x4(v0, v1, v2, v3, addr);
                uint32_t bb0[2] = { v0, v1 };
                uint32_t bb1[2] = { v2, v3 };
                mma_f16(o[2 * dp],     pa[jj], bb0);
                mma_f16(o[2 * dp + 1], pa[jj], bb1);
            }
        }
    }

    l0 += __shfl_xor_sync(0xffffffffu, l0, 1);
    l0 += __shfl_xor_sync(0xffffffffu, l0, 2);
    l1 += __shfl_xor_sync(0xffffffffu, l1, 1);
    l1 += __shfl_xor_sync(0xffffffffu, l1, 2);
    const float inv0 = 1.0f / l0;
    const float inv1 = 1.0f / l1;

    __half* op0 = out + (size_t)r0 * NQ + h * HEAD_DIM + 2 * t;
    __half* op1 = out + (size_t)r1 * NQ + h * HEAD_DIM + 2 * t;
    #pragma unroll
    for (int d = 0; d < 16; d++) {
        *(uint32_t*)(op0 + d * 8) = pack_h2(o[d][0] * inv0, o[d][1] * inv0);
        *(uint32_t*)(op1 + d * 8) = pack_h2(o[d][2] * inv1, o[d][3] * inv1);
    }
}

// ---------------------------------------------------------------------------
// Launch
// ---------------------------------------------------------------------------
extern "C" void kernel_launch(void* const* d_in, const int* in_sizes, int n_in,
                              void* d_out, int out_size)
{
    const float* hidden = (const float*)d_in[0];
    const float* cosb   = (const float*)d_in[1];
    const float* sinb   = (const float*)d_in[2];
    const float* w_qkv  = (const float*)d_in[3];
    const float* b_qkv  = (const float*)d_in[4];
    const float* w_o    = (const float*)d_in[5];
    float* out = (float*)d_out;

    __half *Ah = nullptr, *Bh = nullptr, *Wo = nullptr, *attnh = nullptr;
    cudaGetSymbolAddress((void**)&Ah,    g_Ah);
    cudaGetSymbolAddress((void**)&Bh,    g_Bh);
    cudaGetSymbolAddress((void**)&Wo,    g_Wo);
    cudaGetSymbolAddress((void**)&attnh, g_attnh);

    cudaFuncSetAttribute(gemm_f16<0>, cudaFuncAttributeMaxDynamicSharedMemorySize, GSMEM_BYTES);
    cudaFuncSetAttribute(gemm_f16<1>, cudaFuncAttributeMaxDynamicSharedMemorySize, GSMEM_BYTES);
    cudaFuncSetAttribute(flash_f16,   cudaFuncAttributeMaxDynamicSharedMemorySize, FSMEM_BYTES);

    // 0) fused fp16 conversion of hidden + w_qkv (one launch)
    {
        int total = N16_A + N16_B;
        cvt_both_kernel<<<(total + 255) / 256, 256>>>(hidden, Ah, w_qkv, Bh);
    }

    // 1) QKV projection with fused bias+RoPE+scale(log2e)+fp16+V-transpose
    gemm_f16<1><<<dim3(QKV_OUT / 128, SEQLEN / 128), 256, GSMEM_BYTES>>>(
        Ah, Bh, b_qkv, nullptr, cosb, sinb, HIDDEN, QKV_OUT, QKV_OUT);

    // 2) flash attention (2 CTAs/SM) + overlapped w_o conversion
    flash_f16<<<dim3(FQB + FCVT_X, NUM_HEADS), 128, FSMEM_BYTES>>>(attnh, w_o, Wo);

    // 3) output projection (fp16 mma, fp32 out, 2 CTAs/SM)
    gemm_f16<0><<<dim3(HIDDEN / 128, SEQLEN / 128), 256, GSMEM_BYTES>>>(
        attnh, Wo, nullptr, out, nullptr, nullptr, NQ, HIDDEN, HIDDEN);
}